// round 2
// baseline (speedup 1.0000x reference)
#include <cuda_runtime.h>
#include <math.h>

#define Bdim 128
#define Ldim 256
#define Hdim 512
#define H3   1536
#define OUTD 256
#define BL   (Bdim*Ldim)   // 32768
#define NBLK 128           // persistent kernel grid

// ---------------- scratch (device globals; no allocations allowed) ----------
__device__ float g_xmean[Bdim*Hdim];
__device__ float g_delta[BL*Hdim];
__device__ float g_xhat [BL*Hdim];
__device__ float g_gammah[BL*Hdim];
__device__ float g_pre  [BL*H3];
__device__ float g_hseq [BL*Hdim];
__device__ float g_h    [Bdim*Hdim];
__device__ float g_z    [Bdim*Hdim];
__device__ float g_rh   [Bdim*Hdim];
__device__ unsigned g_arrive = 0;
__device__ volatile unsigned g_release = 0;

// ---------------- grid barrier (all NBLK blocks resident) -------------------
__device__ __forceinline__ void gridbar(unsigned nb) {
    __syncthreads();
    if (threadIdx.x == 0) {
        __threadfence();
        unsigned gen = g_release;
        if (atomicInc(&g_arrive, nb - 1u) == nb - 1u) {
            __threadfence();
            g_release = gen + 1u;
        } else {
            while (g_release == gen) { __nanosleep(64); }
        }
    }
    __syncthreads();
}

__device__ __forceinline__ float sigmoidf_(float x) { return 1.f / (1.f + expf(-x)); }

// ---------------- K1: x_mean -------------------------------------------------
__global__ void __launch_bounds__(256) k_xmean(const float* __restrict__ C,
                                               const int* __restrict__ mask) {
    int idx = blockIdx.x * 256 + threadIdx.x;   // b*512+h
    int b = idx >> 9, h = idx & 511;
    const int* mp = mask + (size_t)b * Ldim * Hdim + h;
    float s = 0.f, cnt = 0.f;
    #pragma unroll 4
    for (int l = 0; l < Ldim; l++) {
        float m = (float)mp[l * Hdim];
        s   += m * C[l * Hdim + h];
        cnt += m;
    }
    g_xmean[idx] = s / fmaxf(cnt, 1.f);
}

// ---------------- K2: elementwise scans (delta, gamma_x, x_hat) -------------
__global__ void __launch_bounds__(256) k_scan(const float* __restrict__ C,
                                              const float* __restrict__ t,
                                              const int* __restrict__ mask,
                                              const float* __restrict__ w_gx,
                                              const float* __restrict__ b_gx) {
    int idx = blockIdx.x * 256 + threadIdx.x;   // b*512+h
    int b = idx >> 9, h = idx & 511;
    float xm = g_xmean[idx];
    float xl = xm, dprev = 0.f, mprev = 1.f, tprev = 0.f;
    float wg = w_gx[h], bg = b_gx[h];
    const int* mp = mask + (size_t)b * Ldim * Hdim + h;
    const float* tp = t + b * Ldim;
    for (int l = 0; l < Ldim; l++) {
        float tc = tp[l];
        float dt = (l == 0) ? 0.f : (tc - tprev);
        tprev = tc;
        float m = (float)mp[l * Hdim];
        float delta = dt + (1.f - mprev) * dprev;
        float gx = expf(-fmaxf(0.f, wg * delta + bg));
        float x  = C[(l << 9) + h];
        int gi = ((b * Ldim + l) << 9) + h;
        g_delta[gi] = delta;
        g_xhat[gi]  = m * x + (1.f - m) * (gx * xl + (1.f - gx) * xm);
        xl = m * x + (1.f - m) * xl;
        dprev = delta; mprev = m;
    }
}

// ---------------- K3: gamma_h = exp(-relu(delta @ W_gh + b_gh)) -------------
__global__ void __launch_bounds__(256) k_gemm_gh(const float* __restrict__ Bw,
                                                 const float* __restrict__ bias) {
    __shared__ float As[64][17];
    __shared__ float Bs[16][64];
    const int tid = threadIdx.x;
    const int bn = blockIdx.x * 64, bm = blockIdx.y * 64;
    const int tx = tid & 15, ty = tid >> 4;
    const int arow = tid >> 2, acol = (tid & 3) * 4;
    const int brow = tid >> 4, bcol = (tid & 15) * 4;
    float acc[4][4] = {};
    for (int k0 = 0; k0 < Hdim; k0 += 16) {
        float4 av = *(const float4*)&g_delta[(size_t)(bm + arow) * Hdim + k0 + acol];
        As[arow][acol + 0] = av.x; As[arow][acol + 1] = av.y;
        As[arow][acol + 2] = av.z; As[arow][acol + 3] = av.w;
        *(float4*)&Bs[brow][bcol] = *(const float4*)&Bw[(size_t)(k0 + brow) * Hdim + bn + bcol];
        __syncthreads();
        #pragma unroll
        for (int k = 0; k < 16; k++) {
            float a0 = As[ty * 4 + 0][k], a1 = As[ty * 4 + 1][k];
            float a2 = As[ty * 4 + 2][k], a3 = As[ty * 4 + 3][k];
            float4 bv = *(float4*)&Bs[k][tx * 4];
            acc[0][0] += a0 * bv.x; acc[0][1] += a0 * bv.y; acc[0][2] += a0 * bv.z; acc[0][3] += a0 * bv.w;
            acc[1][0] += a1 * bv.x; acc[1][1] += a1 * bv.y; acc[1][2] += a1 * bv.z; acc[1][3] += a1 * bv.w;
            acc[2][0] += a2 * bv.x; acc[2][1] += a2 * bv.y; acc[2][2] += a2 * bv.z; acc[2][3] += a2 * bv.w;
            acc[3][0] += a3 * bv.x; acc[3][1] += a3 * bv.y; acc[3][2] += a3 * bv.z; acc[3][3] += a3 * bv.w;
        }
        __syncthreads();
    }
    #pragma unroll
    for (int i = 0; i < 4; i++) {
        int r = bm + ty * 4 + i;
        #pragma unroll
        for (int j = 0; j < 4; j++) {
            int c = bn + tx * 4 + j;
            g_gammah[(size_t)r * Hdim + c] = expf(-fmaxf(0.f, acc[i][j] + bias[c]));
        }
    }
}

// ---------------- K4: pre = x_hat@Wx + m@Wm + b ------------------------------
__global__ void __launch_bounds__(256) k_gemm_pre(const int* __restrict__ mask,
                                                  const float* __restrict__ Wx,
                                                  const float* __restrict__ Wm,
                                                  const float* __restrict__ bias) {
    __shared__ float As[64][17];
    __shared__ float Bs[16][64];
    const int tid = threadIdx.x;
    const int bn = blockIdx.x * 64, bm = blockIdx.y * 64;
    const int tx = tid & 15, ty = tid >> 4;
    const int arow = tid >> 2, acol = (tid & 3) * 4;
    const int brow = tid >> 4, bcol = (tid & 15) * 4;
    float acc[4][4] = {};
    for (int pass = 0; pass < 2; pass++) {
        const float* Bw = pass ? Wm : Wx;
        for (int k0 = 0; k0 < Hdim; k0 += 16) {
            if (pass == 0) {
                float4 av = *(const float4*)&g_xhat[(size_t)(bm + arow) * Hdim + k0 + acol];
                As[arow][acol + 0] = av.x; As[arow][acol + 1] = av.y;
                As[arow][acol + 2] = av.z; As[arow][acol + 3] = av.w;
            } else {
                int4 mv = *(const int4*)&mask[(size_t)(bm + arow) * Hdim + k0 + acol];
                As[arow][acol + 0] = (float)mv.x; As[arow][acol + 1] = (float)mv.y;
                As[arow][acol + 2] = (float)mv.z; As[arow][acol + 3] = (float)mv.w;
            }
            *(float4*)&Bs[brow][bcol] = *(const float4*)&Bw[(size_t)(k0 + brow) * H3 + bn + bcol];
            __syncthreads();
            #pragma unroll
            for (int k = 0; k < 16; k++) {
                float a0 = As[ty * 4 + 0][k], a1 = As[ty * 4 + 1][k];
                float a2 = As[ty * 4 + 2][k], a3 = As[ty * 4 + 3][k];
                float4 bv = *(float4*)&Bs[k][tx * 4];
                acc[0][0] += a0 * bv.x; acc[0][1] += a0 * bv.y; acc[0][2] += a0 * bv.z; acc[0][3] += a0 * bv.w;
                acc[1][0] += a1 * bv.x; acc[1][1] += a1 * bv.y; acc[1][2] += a1 * bv.z; acc[1][3] += a1 * bv.w;
                acc[2][0] += a2 * bv.x; acc[2][1] += a2 * bv.y; acc[2][2] += a2 * bv.z; acc[2][3] += a2 * bv.w;
                acc[3][0] += a3 * bv.x; acc[3][1] += a3 * bv.y; acc[3][2] += a3 * bv.z; acc[3][3] += a3 * bv.w;
            }
            __syncthreads();
        }
    }
    #pragma unroll
    for (int i = 0; i < 4; i++) {
        int r = bm + ty * 4 + i;
        #pragma unroll
        for (int j = 0; j < 4; j++) {
            int c = bn + tx * 4 + j;
            g_pre[(size_t)r * H3 + c] = acc[i][j] + bias[c];
        }
    }
}

// ---------------- K6: out = h_seq @ W_out + b_out ----------------------------
__global__ void __launch_bounds__(256) k_gemm_out(const float* __restrict__ Bw,
                                                  const float* __restrict__ bias,
                                                  float* __restrict__ out) {
    __shared__ float As[64][17];
    __shared__ float Bs[16][64];
    const int tid = threadIdx.x;
    const int bn = blockIdx.x * 64, bm = blockIdx.y * 64;
    const int tx = tid & 15, ty = tid >> 4;
    const int arow = tid >> 2, acol = (tid & 3) * 4;
    const int brow = tid >> 4, bcol = (tid & 15) * 4;
    float acc[4][4] = {};
    for (int k0 = 0; k0 < Hdim; k0 += 16) {
        float4 av = *(const float4*)&g_hseq[(size_t)(bm + arow) * Hdim + k0 + acol];
        As[arow][acol + 0] = av.x; As[arow][acol + 1] = av.y;
        As[arow][acol + 2] = av.z; As[arow][acol + 3] = av.w;
        *(float4*)&Bs[brow][bcol] = *(const float4*)&Bw[(size_t)(k0 + brow) * OUTD + bn + bcol];
        __syncthreads();
        #pragma unroll
        for (int k = 0; k < 16; k++) {
            float a0 = As[ty * 4 + 0][k], a1 = As[ty * 4 + 1][k];
            float a2 = As[ty * 4 + 2][k], a3 = As[ty * 4 + 3][k];
            float4 bv = *(float4*)&Bs[k][tx * 4];
            acc[0][0] += a0 * bv.x; acc[0][1] += a0 * bv.y; acc[0][2] += a0 * bv.z; acc[0][3] += a0 * bv.w;
            acc[1][0] += a1 * bv.x; acc[1][1] += a1 * bv.y; acc[1][2] += a1 * bv.z; acc[1][3] += a1 * bv.w;
            acc[2][0] += a2 * bv.x; acc[2][1] += a2 * bv.y; acc[2][2] += a2 * bv.z; acc[2][3] += a2 * bv.w;
            acc[3][0] += a3 * bv.x; acc[3][1] += a3 * bv.y; acc[3][2] += a3 * bv.z; acc[3][3] += a3 * bv.w;
        }
        __syncthreads();
    }
    #pragma unroll
    for (int i = 0; i < 4; i++) {
        int r = bm + ty * 4 + i;
        #pragma unroll
        for (int j = 0; j < 4; j++) {
            int c = bn + tx * 4 + j;
            out[(size_t)r * OUTD + c] = acc[i][j] + bias[c];
        }
    }
}

// ---------------- K5: persistent sequential recurrence -----------------------
// 128 blocks x 256 threads. Each block owns:
//   GEMM1 tile: rows m0..m0+31 (batch), cols n0..n0+31 of Wh[:, :1024]
//   GEMM2 tile: rows m0..m0+31, cols n02..n02+15 of Wh[:, 1024:1536]
// Wh panels cached in smem for the whole kernel.
__global__ void __launch_bounds__(256, 1) k_seq(const float* __restrict__ Wh) {
    extern __shared__ float sm[];
    float* Wh1p = sm;                    // [512][32]
    float* Wh3p = sm + 512 * 32;         // [512][16]
    float* As   = Wh3p + 512 * 16;       // [2][32][64]

    const int tid = threadIdx.x;
    const int blk = blockIdx.x;
    const int tm = blk & 3;
    const int tn = blk >> 2;             // 0..31
    const int m0  = tm * 32;
    const int n0  = tn * 32;             // GEMM1 col base (0..1023)
    const int n02 = tn * 16;             // GEMM2 col base (0..511)

    // cache Wh panels once
    for (int i = tid; i < 512 * 8; i += 256) {     // 4096 float4s for panel1
        int k = i >> 3; int c4 = (i & 7) * 4;
        *(float4*)&Wh1p[k * 32 + c4] = *(const float4*)&Wh[(size_t)k * H3 + n0 + c4];
    }
    for (int i = tid; i < 512 * 4; i += 256) {     // 2048 float4s for panel3
        int k = i >> 2; int c4 = (i & 3) * 4;
        *(float4*)&Wh3p[k * 16 + c4] = *(const float4*)&Wh[(size_t)k * H3 + 1024 + n02 + c4];
    }
    // init h = 0
    g_h[blk * 512 + tid] = 0.f;
    g_h[blk * 512 + 256 + tid] = 0.f;
    gridbar(NBLK);

    const int row1 = tid >> 3;           // 0..31
    const int cg1  = (tid & 7) * 4;      // GEMM1 col group
    const int c2   = (tid & 7) * 2;      // GEMM2 col pair
    const int ar   = tid >> 3;           // A-loader row (0..31)
    const int ac   = (tid & 7) * 8;      // A-loader col base

    for (int step = 0; step < Ldim; step++) {
        // ================= GEMM1: hd @ Wh[:, n0..n0+31] =================
        float4 acc = {0.f, 0.f, 0.f, 0.f};
        const float* hrow = g_h + (m0 + ar) * 512;
        const float* grow = g_gammah + (size_t)((m0 + ar) * Ldim + step) * 512;
        float4 h0 = __ldcg((const float4*)(hrow + ac));
        float4 h1 = __ldcg((const float4*)(hrow + ac + 4));
        float4 ga0 = *(const float4*)(grow + ac);
        float4 ga1 = *(const float4*)(grow + ac + 4);
        for (int kc = 0; kc < 8; kc++) {
            float* buf = As + (kc & 1) * 2048;
            __syncthreads();
            float4 p0 = make_float4(h0.x * ga0.x, h0.y * ga0.y, h0.z * ga0.z, h0.w * ga0.w);
            float4 p1 = make_float4(h1.x * ga1.x, h1.y * ga1.y, h1.z * ga1.z, h1.w * ga1.w);
            *(float4*)&buf[ar * 64 + ac]     = p0;
            *(float4*)&buf[ar * 64 + ac + 4] = p1;
            __syncthreads();
            if (kc < 7) {
                int k0 = (kc + 1) * 64;
                h0  = __ldcg((const float4*)(hrow + k0 + ac));
                h1  = __ldcg((const float4*)(hrow + k0 + ac + 4));
                ga0 = *(const float4*)(grow + k0 + ac);
                ga1 = *(const float4*)(grow + k0 + ac + 4);
            }
            const float* a  = &buf[row1 * 64];
            const float* bp = &Wh1p[(kc * 64) * 32 + cg1];
            #pragma unroll
            for (int k = 0; k < 64; k++) {
                float av = a[k];
                float4 bv = *(const float4*)&bp[k * 32];
                acc.x += av * bv.x; acc.y += av * bv.y;
                acc.z += av * bv.z; acc.w += av * bv.w;
            }
        }
        { // epilogue GEMM1
            int b = m0 + row1;
            size_t pbase = (size_t)(b * Ldim + step) * H3;
            float av[4] = {acc.x, acc.y, acc.z, acc.w};
            if (n0 < 512) {
                #pragma unroll
                for (int j = 0; j < 4; j++) {
                    int n = n0 + cg1 + j;
                    g_z[b * 512 + n] = sigmoidf_(av[j] + g_pre[pbase + n]);
                }
            } else {
                int gb = (b * Ldim + step) * 512;
                #pragma unroll
                for (int j = 0; j < 4; j++) {
                    int n = n0 + cg1 + j;
                    int jj = n - 512;
                    float s = sigmoidf_(av[j] + g_pre[pbase + n]);
                    float hd = g_gammah[gb + jj] * __ldcg(g_h + b * 512 + jj);
                    g_rh[b * 512 + jj] = s * hd;
                }
            }
        }
        gridbar(NBLK);

        // ================= GEMM2: rh @ Wh[:, 1024+n02 .. +15] ============
        float2 acc2 = {0.f, 0.f};
        const float* rrow = g_rh + (m0 + ar) * 512;
        float4 r0 = __ldcg((const float4*)(rrow + ac));
        float4 r1 = __ldcg((const float4*)(rrow + ac + 4));
        for (int kc = 0; kc < 8; kc++) {
            float* buf = As + (kc & 1) * 2048;
            __syncthreads();
            *(float4*)&buf[ar * 64 + ac]     = r0;
            *(float4*)&buf[ar * 64 + ac + 4] = r1;
            __syncthreads();
            if (kc < 7) {
                int k0 = (kc + 1) * 64;
                r0 = __ldcg((const float4*)(rrow + k0 + ac));
                r1 = __ldcg((const float4*)(rrow + k0 + ac + 4));
            }
            const float* a  = &buf[row1 * 64];
            const float* bp = &Wh3p[(kc * 64) * 16 + c2];
            #pragma unroll
            for (int k = 0; k < 64; k += 2) {
                float2 a2 = *(const float2*)&a[k];
                float2 w0 = *(const float2*)&bp[k * 16];
                float2 w1 = *(const float2*)&bp[(k + 1) * 16];
                acc2.x += a2.x * w0.x + a2.y * w1.x;
                acc2.y += a2.x * w0.y + a2.y * w1.y;
            }
        }
        { // epilogue GEMM2: gates + state update
            int b = m0 + row1;
            size_t pb = (size_t)(b * Ldim + step) * H3 + 1024;
            int gb = (b * Ldim + step) * 512;
            float av[2] = {acc2.x, acc2.y};
            #pragma unroll
            for (int j = 0; j < 2; j++) {
                int n = n02 + c2 + j;
                float ht = tanhf(av[j] + g_pre[pb + n]);
                float hd = g_gammah[gb + n] * __ldcg(g_h + b * 512 + n);
                float z  = __ldcg(g_z + b * 512 + n);
                float hn = (1.f - z) * hd + z * ht;
                g_h[b * 512 + n] = hn;
                g_hseq[gb + n] = hn;
            }
        }
        gridbar(NBLK);
    }
}

// ---------------- launch -----------------------------------------------------
extern "C" void kernel_launch(void* const* d_in, const int* in_sizes, int n_in,
                              void* d_out, int out_size) {
    const float* C     = (const float*)d_in[0];
    const float* t     = (const float*)d_in[1];
    const int*   mask  = (const int*)  d_in[2];
    const float* Wx    = (const float*)d_in[3];
    const float* Wh    = (const float*)d_in[4];
    const float* Wm    = (const float*)d_in[5];
    const float* bvec  = (const float*)d_in[6];
    const float* w_gx  = (const float*)d_in[7];
    const float* b_gx  = (const float*)d_in[8];
    const float* W_gh  = (const float*)d_in[9];
    const float* b_gh  = (const float*)d_in[10];
    const float* W_out = (const float*)d_in[11];
    const float* b_out = (const float*)d_in[12];
    float* out = (float*)d_out;

    const int SMEM_SEQ = (512 * 32 + 512 * 16 + 2 * 32 * 64) * 4;  // 114688 B
    cudaFuncSetAttribute(k_seq, cudaFuncAttributeMaxDynamicSharedMemorySize, SMEM_SEQ);

    k_xmean<<<Bdim * Hdim / 256, 256>>>(C, mask);
    k_scan <<<Bdim * Hdim / 256, 256>>>(C, t, mask, w_gx, b_gx);
    k_gemm_gh <<<dim3(Hdim / 64, BL / 64), 256>>>(W_gh, b_gh);
    k_gemm_pre<<<dim3(H3 / 64,  BL / 64), 256>>>(mask, Wx, Wm, bvec);
    k_seq<<<NBLK, 256, SMEM_SEQ>>>(Wh);
    k_gemm_out<<<dim3(OUTD / 64, BL / 64), 256>>>(W_out, b_out, out);
}

// round 3
// speedup vs baseline: 1.2782x; 1.2782x over previous
#include <cuda_runtime.h>
#include <math.h>

#define Bdim 128
#define Ldim 256
#define Hdim 512
#define H3   1536
#define OUTD 256
#define BL   (Bdim*Ldim)   // 32768
#define NBLK 128           // persistent kernel grid

// ---------------- scratch (device globals; no allocations allowed) ----------
__device__ float g_xmean[Bdim*Hdim];
__device__ float g_delta[BL*Hdim];
__device__ float g_xhat [BL*Hdim];
__device__ float g_gammah[BL*Hdim];
__device__ float g_pre  [BL*H3];
__device__ float g_hseq [BL*Hdim];
__device__ float g_h    [Bdim*Hdim];
__device__ float g_z    [Bdim*Hdim];
__device__ float g_rh   [Bdim*Hdim];
__device__ unsigned g_arrive = 0;
__device__ volatile unsigned g_release = 0;

// ---------------- grid barrier (all NBLK blocks resident) -------------------
__device__ __forceinline__ void gridbar(unsigned nb) {
    __syncthreads();
    if (threadIdx.x == 0) {
        __threadfence();
        unsigned gen = g_release;
        if (atomicInc(&g_arrive, nb - 1u) == nb - 1u) {
            __threadfence();
            g_release = gen + 1u;
        } else {
            while (g_release == gen) { __nanosleep(64); }
        }
    }
    __syncthreads();
}

__device__ __forceinline__ float sigmoidf_(float x) { return 1.f / (1.f + expf(-x)); }

__device__ __forceinline__ unsigned f2tf32(float f) {
    unsigned r; asm("cvt.rna.tf32.f32 %0, %1;" : "=r"(r) : "f"(f)); return r;
}
__device__ __forceinline__ void mma_tf32(float* c, const unsigned* a, const unsigned* b) {
    asm volatile("mma.sync.aligned.m16n8k8.row.col.f32.tf32.tf32.f32 "
        "{%0,%1,%2,%3}, {%4,%5,%6,%7}, {%8,%9}, {%0,%1,%2,%3};"
        : "+f"(c[0]), "+f"(c[1]), "+f"(c[2]), "+f"(c[3])
        : "r"(a[0]), "r"(a[1]), "r"(a[2]), "r"(a[3]), "r"(b[0]), "r"(b[1]));
}

// ---------------- K1: x_mean -------------------------------------------------
__global__ void __launch_bounds__(256) k_xmean(const float* __restrict__ C,
                                               const int* __restrict__ mask) {
    int idx = blockIdx.x * 256 + threadIdx.x;   // b*512+h
    int b = idx >> 9, h = idx & 511;
    const int* mp = mask + (size_t)b * Ldim * Hdim + h;
    float s = 0.f, cnt = 0.f;
    #pragma unroll 4
    for (int l = 0; l < Ldim; l++) {
        float m = (float)mp[l * Hdim];
        s   += m * C[l * Hdim + h];
        cnt += m;
    }
    g_xmean[idx] = s / fmaxf(cnt, 1.f);
}

// ---------------- K2: elementwise scans (delta, gamma_x, x_hat) -------------
__global__ void __launch_bounds__(256) k_scan(const float* __restrict__ C,
                                              const float* __restrict__ t,
                                              const int* __restrict__ mask,
                                              const float* __restrict__ w_gx,
                                              const float* __restrict__ b_gx) {
    int idx = blockIdx.x * 256 + threadIdx.x;   // b*512+h
    int b = idx >> 9, h = idx & 511;
    float xm = g_xmean[idx];
    float xl = xm, dprev = 0.f, mprev = 1.f, tprev = 0.f;
    float wg = w_gx[h], bg = b_gx[h];
    const int* mp = mask + (size_t)b * Ldim * Hdim + h;
    const float* tp = t + b * Ldim;
    for (int l = 0; l < Ldim; l++) {
        float tc = tp[l];
        float dt = (l == 0) ? 0.f : (tc - tprev);
        tprev = tc;
        float m = (float)mp[l * Hdim];
        float delta = dt + (1.f - mprev) * dprev;
        float gx = expf(-fmaxf(0.f, wg * delta + bg));
        float x  = C[(l << 9) + h];
        int gi = ((b * Ldim + l) << 9) + h;
        g_delta[gi] = delta;
        g_xhat[gi]  = m * x + (1.f - m) * (gx * xl + (1.f - gx) * xm);
        xl = m * x + (1.f - m) * xl;
        dprev = delta; mprev = m;
    }
}

// =============================================================================
// tf32 tensor-core GEMM machinery: 128x128x16 tiles, 256 threads (8 warps 2x4),
// double-buffered smem. A stride 20 / B stride 136 -> conflict-free frag reads.
// =============================================================================
#define ASTR 20
#define BSTR 136

// ---------------- K3 (mma): gamma_h = exp(-relu(delta @ W_gh + b_gh)) -------
__global__ void __launch_bounds__(256) k_gh_mma(const float* __restrict__ Bw,
                                                const float* __restrict__ bias) {
    __shared__ unsigned As[2][128 * ASTR];
    __shared__ unsigned Bs[2][16 * BSTR];
    const int tid = threadIdx.x;
    const int bn = blockIdx.x * 128, bm = blockIdx.y * 128;
    const int wid = tid >> 5, lane = tid & 31;
    const int wm = (wid >> 2) * 64, wn = (wid & 3) * 32;
    const int g = lane >> 2, tg = lane & 3;
    const int arow = tid >> 2, ac4 = (tid & 3) * 4;
    const int brow = tid >> 5, bc4 = lane * 4;

    float acc[4][4][4];
    #pragma unroll
    for (int i = 0; i < 4; i++)
        #pragma unroll
        for (int j = 0; j < 4; j++)
            #pragma unroll
            for (int q = 0; q < 4; q++) acc[i][j][q] = 0.f;

    float4 av0, av1, bv0, bv1;
    // prefetch tile 0
    av0 = *(const float4*)&g_delta[(size_t)(bm + arow) * Hdim + ac4];
    av1 = *(const float4*)&g_delta[(size_t)(bm + arow + 64) * Hdim + ac4];
    bv0 = *(const float4*)&Bw[(size_t)(brow) * Hdim + bn + bc4];
    bv1 = *(const float4*)&Bw[(size_t)(brow + 8) * Hdim + bn + bc4];
    {
        unsigned* A = As[0]; unsigned* B = Bs[0];
        A[arow * ASTR + ac4 + 0] = f2tf32(av0.x); A[arow * ASTR + ac4 + 1] = f2tf32(av0.y);
        A[arow * ASTR + ac4 + 2] = f2tf32(av0.z); A[arow * ASTR + ac4 + 3] = f2tf32(av0.w);
        A[(arow + 64) * ASTR + ac4 + 0] = f2tf32(av1.x); A[(arow + 64) * ASTR + ac4 + 1] = f2tf32(av1.y);
        A[(arow + 64) * ASTR + ac4 + 2] = f2tf32(av1.z); A[(arow + 64) * ASTR + ac4 + 3] = f2tf32(av1.w);
        B[brow * BSTR + bc4 + 0] = f2tf32(bv0.x); B[brow * BSTR + bc4 + 1] = f2tf32(bv0.y);
        B[brow * BSTR + bc4 + 2] = f2tf32(bv0.z); B[brow * BSTR + bc4 + 3] = f2tf32(bv0.w);
        B[(brow + 8) * BSTR + bc4 + 0] = f2tf32(bv1.x); B[(brow + 8) * BSTR + bc4 + 1] = f2tf32(bv1.y);
        B[(brow + 8) * BSTR + bc4 + 2] = f2tf32(bv1.z); B[(brow + 8) * BSTR + bc4 + 3] = f2tf32(bv1.w);
    }
    __syncthreads();

    const int KT = Hdim / 16;  // 32
    for (int kt = 0; kt < KT; kt++) {
        if (kt + 1 < KT) {
            int k0 = (kt + 1) * 16;
            av0 = *(const float4*)&g_delta[(size_t)(bm + arow) * Hdim + k0 + ac4];
            av1 = *(const float4*)&g_delta[(size_t)(bm + arow + 64) * Hdim + k0 + ac4];
            bv0 = *(const float4*)&Bw[(size_t)(k0 + brow) * Hdim + bn + bc4];
            bv1 = *(const float4*)&Bw[(size_t)(k0 + brow + 8) * Hdim + bn + bc4];
        }
        const unsigned* A = As[kt & 1];
        const unsigned* B = Bs[kt & 1];
        #pragma unroll
        for (int ks = 0; ks < 2; ks++) {
            unsigned af[4][4], bf[4][2];
            #pragma unroll
            for (int mt = 0; mt < 4; mt++) {
                int mb = wm + mt * 16;
                af[mt][0] = A[(mb + g) * ASTR + ks * 8 + tg];
                af[mt][1] = A[(mb + g + 8) * ASTR + ks * 8 + tg];
                af[mt][2] = A[(mb + g) * ASTR + ks * 8 + tg + 4];
                af[mt][3] = A[(mb + g + 8) * ASTR + ks * 8 + tg + 4];
            }
            #pragma unroll
            for (int nt = 0; nt < 4; nt++) {
                int nb = wn + nt * 8;
                bf[nt][0] = B[(ks * 8 + tg) * BSTR + nb + g];
                bf[nt][1] = B[(ks * 8 + tg + 4) * BSTR + nb + g];
            }
            #pragma unroll
            for (int mt = 0; mt < 4; mt++)
                #pragma unroll
                for (int nt = 0; nt < 4; nt++)
                    mma_tf32(acc[mt][nt], af[mt], bf[nt]);
        }
        if (kt + 1 < KT) {
            unsigned* An = As[(kt + 1) & 1]; unsigned* Bn = Bs[(kt + 1) & 1];
            An[arow * ASTR + ac4 + 0] = f2tf32(av0.x); An[arow * ASTR + ac4 + 1] = f2tf32(av0.y);
            An[arow * ASTR + ac4 + 2] = f2tf32(av0.z); An[arow * ASTR + ac4 + 3] = f2tf32(av0.w);
            An[(arow + 64) * ASTR + ac4 + 0] = f2tf32(av1.x); An[(arow + 64) * ASTR + ac4 + 1] = f2tf32(av1.y);
            An[(arow + 64) * ASTR + ac4 + 2] = f2tf32(av1.z); An[(arow + 64) * ASTR + ac4 + 3] = f2tf32(av1.w);
            Bn[brow * BSTR + bc4 + 0] = f2tf32(bv0.x); Bn[brow * BSTR + bc4 + 1] = f2tf32(bv0.y);
            Bn[brow * BSTR + bc4 + 2] = f2tf32(bv0.z); Bn[brow * BSTR + bc4 + 3] = f2tf32(bv0.w);
            Bn[(brow + 8) * BSTR + bc4 + 0] = f2tf32(bv1.x); Bn[(brow + 8) * BSTR + bc4 + 1] = f2tf32(bv1.y);
            Bn[(brow + 8) * BSTR + bc4 + 2] = f2tf32(bv1.z); Bn[(brow + 8) * BSTR + bc4 + 3] = f2tf32(bv1.w);
        }
        __syncthreads();
    }

    #pragma unroll
    for (int mt = 0; mt < 4; mt++) {
        #pragma unroll
        for (int nt = 0; nt < 4; nt++) {
            int col = bn + wn + nt * 8 + tg * 2;
            float b0 = bias[col], b1 = bias[col + 1];
            int r0 = bm + wm + mt * 16 + g;
            float2 o0, o1;
            o0.x = expf(-fmaxf(0.f, acc[mt][nt][0] + b0));
            o0.y = expf(-fmaxf(0.f, acc[mt][nt][1] + b1));
            o1.x = expf(-fmaxf(0.f, acc[mt][nt][2] + b0));
            o1.y = expf(-fmaxf(0.f, acc[mt][nt][3] + b1));
            *(float2*)&g_gammah[(size_t)r0 * Hdim + col] = o0;
            *(float2*)&g_gammah[(size_t)(r0 + 8) * Hdim + col] = o1;
        }
    }
}

// ---------------- K4 (mma): pre = x_hat@Wx + m@Wm + b ------------------------
// K is virtualized to 1024: kt<32 -> (x_hat, Wx), kt>=32 -> (mask, Wm)
__global__ void __launch_bounds__(256) k_pre_mma(const int* __restrict__ mask,
                                                 const float* __restrict__ Wx,
                                                 const float* __restrict__ Wm,
                                                 const float* __restrict__ bias) {
    __shared__ unsigned As[2][128 * ASTR];
    __shared__ unsigned Bs[2][16 * BSTR];
    const int tid = threadIdx.x;
    const int bn = blockIdx.x * 128, bm = blockIdx.y * 128;
    const int wid = tid >> 5, lane = tid & 31;
    const int wm = (wid >> 2) * 64, wn = (wid & 3) * 32;
    const int g = lane >> 2, tg = lane & 3;
    const int arow = tid >> 2, ac4 = (tid & 3) * 4;
    const int brow = tid >> 5, bc4 = lane * 4;

    float acc[4][4][4];
    #pragma unroll
    for (int i = 0; i < 4; i++)
        #pragma unroll
        for (int j = 0; j < 4; j++)
            #pragma unroll
            for (int q = 0; q < 4; q++) acc[i][j][q] = 0.f;

    float4 av0, av1, bv0, bv1;

    // prefetch tile 0 (pass 0: x_hat / Wx)
    av0 = *(const float4*)&g_xhat[(size_t)(bm + arow) * Hdim + ac4];
    av1 = *(const float4*)&g_xhat[(size_t)(bm + arow + 64) * Hdim + ac4];
    bv0 = *(const float4*)&Wx[(size_t)(brow) * H3 + bn + bc4];
    bv1 = *(const float4*)&Wx[(size_t)(brow + 8) * H3 + bn + bc4];
    {
        unsigned* A = As[0]; unsigned* B = Bs[0];
        A[arow * ASTR + ac4 + 0] = f2tf32(av0.x); A[arow * ASTR + ac4 + 1] = f2tf32(av0.y);
        A[arow * ASTR + ac4 + 2] = f2tf32(av0.z); A[arow * ASTR + ac4 + 3] = f2tf32(av0.w);
        A[(arow + 64) * ASTR + ac4 + 0] = f2tf32(av1.x); A[(arow + 64) * ASTR + ac4 + 1] = f2tf32(av1.y);
        A[(arow + 64) * ASTR + ac4 + 2] = f2tf32(av1.z); A[(arow + 64) * ASTR + ac4 + 3] = f2tf32(av1.w);
        B[brow * BSTR + bc4 + 0] = f2tf32(bv0.x); B[brow * BSTR + bc4 + 1] = f2tf32(bv0.y);
        B[brow * BSTR + bc4 + 2] = f2tf32(bv0.z); B[brow * BSTR + bc4 + 3] = f2tf32(bv0.w);
        B[(brow + 8) * BSTR + bc4 + 0] = f2tf32(bv1.x); B[(brow + 8) * BSTR + bc4 + 1] = f2tf32(bv1.y);
        B[(brow + 8) * BSTR + bc4 + 2] = f2tf32(bv1.z); B[(brow + 8) * BSTR + bc4 + 3] = f2tf32(bv1.w);
    }
    __syncthreads();

    const int KT = 64;  // 2 passes x 32
    for (int kt = 0; kt < KT; kt++) {
        if (kt + 1 < KT) {
            int nkt = kt + 1;
            int k0 = (nkt & 31) * 16;
            if (nkt < 32) {
                av0 = *(const float4*)&g_xhat[(size_t)(bm + arow) * Hdim + k0 + ac4];
                av1 = *(const float4*)&g_xhat[(size_t)(bm + arow + 64) * Hdim + k0 + ac4];
                bv0 = *(const float4*)&Wx[(size_t)(k0 + brow) * H3 + bn + bc4];
                bv1 = *(const float4*)&Wx[(size_t)(k0 + brow + 8) * H3 + bn + bc4];
            } else {
                int4 m0 = *(const int4*)&mask[(size_t)(bm + arow) * Hdim + k0 + ac4];
                int4 m1 = *(const int4*)&mask[(size_t)(bm + arow + 64) * Hdim + k0 + ac4];
                av0 = make_float4((float)m0.x, (float)m0.y, (float)m0.z, (float)m0.w);
                av1 = make_float4((float)m1.x, (float)m1.y, (float)m1.z, (float)m1.w);
                bv0 = *(const float4*)&Wm[(size_t)(k0 + brow) * H3 + bn + bc4];
                bv1 = *(const float4*)&Wm[(size_t)(k0 + brow + 8) * H3 + bn + bc4];
            }
        }
        const unsigned* A = As[kt & 1];
        const unsigned* B = Bs[kt & 1];
        #pragma unroll
        for (int ks = 0; ks < 2; ks++) {
            unsigned af[4][4], bf[4][2];
            #pragma unroll
            for (int mt = 0; mt < 4; mt++) {
                int mb = wm + mt * 16;
                af[mt][0] = A[(mb + g) * ASTR + ks * 8 + tg];
                af[mt][1] = A[(mb + g + 8) * ASTR + ks * 8 + tg];
                af[mt][2] = A[(mb + g) * ASTR + ks * 8 + tg + 4];
                af[mt][3] = A[(mb + g + 8) * ASTR + ks * 8 + tg + 4];
            }
            #pragma unroll
            for (int nt = 0; nt < 4; nt++) {
                int nb = wn + nt * 8;
                bf[nt][0] = B[(ks * 8 + tg) * BSTR + nb + g];
                bf[nt][1] = B[(ks * 8 + tg + 4) * BSTR + nb + g];
            }
            #pragma unroll
            for (int mt = 0; mt < 4; mt++)
                #pragma unroll
                for (int nt = 0; nt < 4; nt++)
                    mma_tf32(acc[mt][nt], af[mt], bf[nt]);
        }
        if (kt + 1 < KT) {
            unsigned* An = As[(kt + 1) & 1]; unsigned* Bn = Bs[(kt + 1) & 1];
            An[arow * ASTR + ac4 + 0] = f2tf32(av0.x); An[arow * ASTR + ac4 + 1] = f2tf32(av0.y);
            An[arow * ASTR + ac4 + 2] = f2tf32(av0.z); An[arow * ASTR + ac4 + 3] = f2tf32(av0.w);
            An[(arow + 64) * ASTR + ac4 + 0] = f2tf32(av1.x); An[(arow + 64) * ASTR + ac4 + 1] = f2tf32(av1.y);
            An[(arow + 64) * ASTR + ac4 + 2] = f2tf32(av1.z); An[(arow + 64) * ASTR + ac4 + 3] = f2tf32(av1.w);
            Bn[brow * BSTR + bc4 + 0] = f2tf32(bv0.x); Bn[brow * BSTR + bc4 + 1] = f2tf32(bv0.y);
            Bn[brow * BSTR + bc4 + 2] = f2tf32(bv0.z); Bn[brow * BSTR + bc4 + 3] = f2tf32(bv0.w);
            Bn[(brow + 8) * BSTR + bc4 + 0] = f2tf32(bv1.x); Bn[(brow + 8) * BSTR + bc4 + 1] = f2tf32(bv1.y);
            Bn[(brow + 8) * BSTR + bc4 + 2] = f2tf32(bv1.z); Bn[(brow + 8) * BSTR + bc4 + 3] = f2tf32(bv1.w);
        }
        __syncthreads();
    }

    #pragma unroll
    for (int mt = 0; mt < 4; mt++) {
        #pragma unroll
        for (int nt = 0; nt < 4; nt++) {
            int col = bn + wn + nt * 8 + tg * 2;
            float b0 = bias[col], b1 = bias[col + 1];
            int r0 = bm + wm + mt * 16 + g;
            float2 o0, o1;
            o0.x = acc[mt][nt][0] + b0; o0.y = acc[mt][nt][1] + b1;
            o1.x = acc[mt][nt][2] + b0; o1.y = acc[mt][nt][3] + b1;
            *(float2*)&g_pre[(size_t)r0 * H3 + col] = o0;
            *(float2*)&g_pre[(size_t)(r0 + 8) * H3 + col] = o1;
        }
    }
}

// ---------------- K6: out = h_seq @ W_out + b_out (fp32, small) --------------
__global__ void __launch_bounds__(256) k_gemm_out(const float* __restrict__ Bw,
                                                  const float* __restrict__ bias,
                                                  float* __restrict__ out) {
    __shared__ float As[64][17];
    __shared__ float Bs[16][64];
    const int tid = threadIdx.x;
    const int bn = blockIdx.x * 64, bm = blockIdx.y * 64;
    const int tx = tid & 15, ty = tid >> 4;
    const int arow = tid >> 2, acol = (tid & 3) * 4;
    const int brow = tid >> 4, bcol = (tid & 15) * 4;
    float acc[4][4] = {};
    for (int k0 = 0; k0 < Hdim; k0 += 16) {
        float4 av = *(const float4*)&g_hseq[(size_t)(bm + arow) * Hdim + k0 + acol];
        As[arow][acol + 0] = av.x; As[arow][acol + 1] = av.y;
        As[arow][acol + 2] = av.z; As[arow][acol + 3] = av.w;
        *(float4*)&Bs[brow][bcol] = *(const float4*)&Bw[(size_t)(k0 + brow) * OUTD + bn + bcol];
        __syncthreads();
        #pragma unroll
        for (int k = 0; k < 16; k++) {
            float a0 = As[ty * 4 + 0][k], a1 = As[ty * 4 + 1][k];
            float a2 = As[ty * 4 + 2][k], a3 = As[ty * 4 + 3][k];
            float4 bv = *(float4*)&Bs[k][tx * 4];
            acc[0][0] += a0 * bv.x; acc[0][1] += a0 * bv.y; acc[0][2] += a0 * bv.z; acc[0][3] += a0 * bv.w;
            acc[1][0] += a1 * bv.x; acc[1][1] += a1 * bv.y; acc[1][2] += a1 * bv.z; acc[1][3] += a1 * bv.w;
            acc[2][0] += a2 * bv.x; acc[2][1] += a2 * bv.y; acc[2][2] += a2 * bv.z; acc[2][3] += a2 * bv.w;
            acc[3][0] += a3 * bv.x; acc[3][1] += a3 * bv.y; acc[3][2] += a3 * bv.z; acc[3][3] += a3 * bv.w;
        }
        __syncthreads();
    }
    #pragma unroll
    for (int i = 0; i < 4; i++) {
        int r = bm + ty * 4 + i;
        #pragma unroll
        for (int j = 0; j < 4; j++) {
            int c = bn + tx * 4 + j;
            out[(size_t)r * OUTD + c] = acc[i][j] + bias[c];
        }
    }
}

// ---------------- K5: persistent sequential recurrence -----------------------
__global__ void __launch_bounds__(256, 1) k_seq(const float* __restrict__ Wh) {
    extern __shared__ float sm[];
    float* Wh1p = sm;                    // [512][32]
    float* Wh3p = sm + 512 * 32;         // [512][16]
    float* As   = Wh3p + 512 * 16;       // [2][32][64]

    const int tid = threadIdx.x;
    const int blk = blockIdx.x;
    const int tm = blk & 3;
    const int tn = blk >> 2;             // 0..31
    const int m0  = tm * 32;
    const int n0  = tn * 32;             // GEMM1 col base (0..1023)
    const int n02 = tn * 16;             // GEMM2 col base (0..511)

    // cache Wh panels once
    for (int i = tid; i < 512 * 8; i += 256) {
        int k = i >> 3; int c4 = (i & 7) * 4;
        *(float4*)&Wh1p[k * 32 + c4] = *(const float4*)&Wh[(size_t)k * H3 + n0 + c4];
    }
    for (int i = tid; i < 512 * 4; i += 256) {
        int k = i >> 2; int c4 = (i & 3) * 4;
        *(float4*)&Wh3p[k * 16 + c4] = *(const float4*)&Wh[(size_t)k * H3 + 1024 + n02 + c4];
    }
    g_h[blk * 512 + tid] = 0.f;
    g_h[blk * 512 + 256 + tid] = 0.f;
    gridbar(NBLK);

    const int row1 = tid >> 3;
    const int cg1  = (tid & 7) * 4;
    const int c2   = (tid & 7) * 2;
    const int ar   = tid >> 3;
    const int ac   = (tid & 7) * 8;

    for (int step = 0; step < Ldim; step++) {
        // ================= GEMM1: hd @ Wh[:, n0..n0+31] =================
        float4 acc = {0.f, 0.f, 0.f, 0.f};
        const float* hrow = g_h + (m0 + ar) * 512;
        const float* grow = g_gammah + (size_t)((m0 + ar) * Ldim + step) * 512;
        float4 h0 = __ldcg((const float4*)(hrow + ac));
        float4 h1 = __ldcg((const float4*)(hrow + ac + 4));
        float4 ga0 = *(const float4*)(grow + ac);
        float4 ga1 = *(const float4*)(grow + ac + 4);
        for (int kc = 0; kc < 8; kc++) {
            float* buf = As + (kc & 1) * 2048;
            __syncthreads();
            float4 p0 = make_float4(h0.x * ga0.x, h0.y * ga0.y, h0.z * ga0.z, h0.w * ga0.w);
            float4 p1 = make_float4(h1.x * ga1.x, h1.y * ga1.y, h1.z * ga1.z, h1.w * ga1.w);
            *(float4*)&buf[ar * 64 + ac]     = p0;
            *(float4*)&buf[ar * 64 + ac + 4] = p1;
            __syncthreads();
            if (kc < 7) {
                int k0 = (kc + 1) * 64;
                h0  = __ldcg((const float4*)(hrow + k0 + ac));
                h1  = __ldcg((const float4*)(hrow + k0 + ac + 4));
                ga0 = *(const float4*)(grow + k0 + ac);
                ga1 = *(const float4*)(grow + k0 + ac + 4);
            }
            const float* a  = &buf[row1 * 64];
            const float* bp = &Wh1p[(kc * 64) * 32 + cg1];
            #pragma unroll
            for (int k = 0; k < 64; k++) {
                float av = a[k];
                float4 bv = *(const float4*)&bp[k * 32];
                acc.x += av * bv.x; acc.y += av * bv.y;
                acc.z += av * bv.z; acc.w += av * bv.w;
            }
        }
        {
            int b = m0 + row1;
            size_t pbase = (size_t)(b * Ldim + step) * H3;
            float av[4] = {acc.x, acc.y, acc.z, acc.w};
            if (n0 < 512) {
                #pragma unroll
                for (int j = 0; j < 4; j++) {
                    int n = n0 + cg1 + j;
                    g_z[b * 512 + n] = sigmoidf_(av[j] + g_pre[pbase + n]);
                }
            } else {
                int gb = (b * Ldim + step) * 512;
                #pragma unroll
                for (int j = 0; j < 4; j++) {
                    int n = n0 + cg1 + j;
                    int jj = n - 512;
                    float s = sigmoidf_(av[j] + g_pre[pbase + n]);
                    float hd = g_gammah[gb + jj] * __ldcg(g_h + b * 512 + jj);
                    g_rh[b * 512 + jj] = s * hd;
                }
            }
        }
        gridbar(NBLK);

        // ================= GEMM2: rh @ Wh[:, 1024+n02 .. +15] ============
        float2 acc2 = {0.f, 0.f};
        const float* rrow = g_rh + (m0 + ar) * 512;
        float4 r0 = __ldcg((const float4*)(rrow + ac));
        float4 r1 = __ldcg((const float4*)(rrow + ac + 4));
        for (int kc = 0; kc < 8; kc++) {
            float* buf = As + (kc & 1) * 2048;
            __syncthreads();
            *(float4*)&buf[ar * 64 + ac]     = r0;
            *(float4*)&buf[ar * 64 + ac + 4] = r1;
            __syncthreads();
            if (kc < 7) {
                int k0 = (kc + 1) * 64;
                r0 = __ldcg((const float4*)(rrow + k0 + ac));
                r1 = __ldcg((const float4*)(rrow + k0 + ac + 4));
            }
            const float* a  = &buf[row1 * 64];
            const float* bp = &Wh3p[(kc * 64) * 16 + c2];
            #pragma unroll
            for (int k = 0; k < 64; k += 2) {
                float2 a2 = *(const float2*)&a[k];
                float2 w0 = *(const float2*)&bp[k * 16];
                float2 w1 = *(const float2*)&bp[(k + 1) * 16];
                acc2.x += a2.x * w0.x + a2.y * w1.x;
                acc2.y += a2.x * w0.y + a2.y * w1.y;
            }
        }
        {
            int b = m0 + row1;
            size_t pb = (size_t)(b * Ldim + step) * H3 + 1024;
            int gb = (b * Ldim + step) * 512;
            float av[2] = {acc2.x, acc2.y};
            #pragma unroll
            for (int j = 0; j < 2; j++) {
                int n = n02 + c2 + j;
                float ht = tanhf(av[j] + g_pre[pb + n]);
                float hd = g_gammah[gb + n] * __ldcg(g_h + b * 512 + n);
                float z  = __ldcg(g_z + b * 512 + n);
                float hn = (1.f - z) * hd + z * ht;
                g_h[b * 512 + n] = hn;
                g_hseq[gb + n] = hn;
            }
        }
        gridbar(NBLK);
    }
}

// ---------------- launch -----------------------------------------------------
extern "C" void kernel_launch(void* const* d_in, const int* in_sizes, int n_in,
                              void* d_out, int out_size) {
    const float* C     = (const float*)d_in[0];
    const float* t     = (const float*)d_in[1];
    const int*   mask  = (const int*)  d_in[2];
    const float* Wx    = (const float*)d_in[3];
    const float* Wh    = (const float*)d_in[4];
    const float* Wm    = (const float*)d_in[5];
    const float* bvec  = (const float*)d_in[6];
    const float* w_gx  = (const float*)d_in[7];
    const float* b_gx  = (const float*)d_in[8];
    const float* W_gh  = (const float*)d_in[9];
    const float* b_gh  = (const float*)d_in[10];
    const float* W_out = (const float*)d_in[11];
    const float* b_out = (const float*)d_in[12];
    float* out = (float*)d_out;

    const int SMEM_SEQ = (512 * 32 + 512 * 16 + 2 * 32 * 64) * 4;  // 114688 B
    cudaFuncSetAttribute(k_seq, cudaFuncAttributeMaxDynamicSharedMemorySize, SMEM_SEQ);

    k_xmean<<<Bdim * Hdim / 256, 256>>>(C, mask);
    k_scan <<<Bdim * Hdim / 256, 256>>>(C, t, mask, w_gx, b_gx);
    k_gh_mma <<<dim3(Hdim / 128, BL / 128), 256>>>(W_gh, b_gh);
    k_pre_mma<<<dim3(H3 / 128,  BL / 128), 256>>>(mask, Wx, Wm, bvec);
    k_seq<<<NBLK, 256, SMEM_SEQ>>>(Wh);
    k_gemm_out<<<dim3(OUTD / 64, BL / 64), 256>>>(W_out, b_out, out);
}

// round 4
// speedup vs baseline: 2.3406x; 1.8311x over previous
#include <cuda_runtime.h>
#include <math.h>

#define Bdim 128
#define Ldim 256
#define Hdim 512
#define H3   1536
#define OUTD 256
#define BL   (Bdim*Ldim)   // 32768
#define NBLK 128

// ---------------- scratch (device globals) ----------------------------------
__device__ float g_xmean[Bdim*Hdim];
__device__ float g_delta[BL*Hdim];
__device__ float g_xhat [BL*Hdim];
__device__ float g_gammah[BL*Hdim];
__device__ float g_pre  [BL*H3];
__device__ float g_hseq [BL*Hdim];
__device__ float g_h    [Bdim*Hdim];
__device__ float g_z    [Bdim*Hdim];
__device__ float g_rh   [Bdim*Hdim];
__device__ unsigned g_arr4[4*32];            // one counter per 128B line
__device__ volatile unsigned g_rel4[4*32];

// ---------------- per-row-group barrier (32 blocks) -------------------------
__device__ __forceinline__ void groupbar(int rg) {
    __syncthreads();
    if (threadIdx.x == 0) {
        __threadfence();
        unsigned gen = g_rel4[rg * 32];
        if (atomicInc((unsigned*)&g_arr4[rg * 32], 31u) == 31u) {
            __threadfence();
            g_rel4[rg * 32] = gen + 1u;
        } else {
            while (g_rel4[rg * 32] == gen) { __nanosleep(32); }
        }
    }
    __syncthreads();
}

__device__ __forceinline__ float sigmoidf_(float x) { return 1.f / (1.f + expf(-x)); }

typedef unsigned long long ull;
__device__ __forceinline__ void ffma2(ull& d, ull a, ull b) {
    asm("fma.rn.f32x2 %0, %1, %2, %0;" : "+l"(d) : "l"(a), "l"(b));
}
__device__ __forceinline__ ull pack2(float x) {
    ull r; asm("mov.b64 %0, {%1, %1};" : "=l"(r) : "f"(x)); return r;
}
__device__ __forceinline__ float2 unpack2(ull v) {
    float2 f; asm("mov.b64 {%0, %1}, %2;" : "=f"(f.x), "=f"(f.y) : "l"(v)); return f;
}

__device__ __forceinline__ unsigned f2tf32(float f) {
    unsigned r; asm("cvt.rna.tf32.f32 %0, %1;" : "=r"(r) : "f"(f)); return r;
}
__device__ __forceinline__ void mma_tf32(float* c, const unsigned* a, const unsigned* b) {
    asm volatile("mma.sync.aligned.m16n8k8.row.col.f32.tf32.tf32.f32 "
        "{%0,%1,%2,%3}, {%4,%5,%6,%7}, {%8,%9}, {%0,%1,%2,%3};"
        : "+f"(c[0]), "+f"(c[1]), "+f"(c[2]), "+f"(c[3])
        : "r"(a[0]), "r"(a[1]), "r"(a[2]), "r"(a[3]), "r"(b[0]), "r"(b[1]));
}

// ---------------- K1: x_mean -------------------------------------------------
__global__ void __launch_bounds__(256) k_xmean(const float* __restrict__ C,
                                               const int* __restrict__ mask) {
    int idx = blockIdx.x * 256 + threadIdx.x;
    int b = idx >> 9, h = idx & 511;
    const int* mp = mask + (size_t)b * Ldim * Hdim + h;
    float s = 0.f, cnt = 0.f;
    #pragma unroll 4
    for (int l = 0; l < Ldim; l++) {
        float m = (float)mp[l * Hdim];
        s   += m * C[l * Hdim + h];
        cnt += m;
    }
    g_xmean[idx] = s / fmaxf(cnt, 1.f);
}

// ---------------- K2: elementwise scans --------------------------------------
__global__ void __launch_bounds__(256) k_scan(const float* __restrict__ C,
                                              const float* __restrict__ t,
                                              const int* __restrict__ mask,
                                              const float* __restrict__ w_gx,
                                              const float* __restrict__ b_gx) {
    int idx = blockIdx.x * 256 + threadIdx.x;
    int b = idx >> 9, h = idx & 511;
    float xm = g_xmean[idx];
    float xl = xm, dprev = 0.f, mprev = 1.f, tprev = 0.f;
    float wg = w_gx[h], bg = b_gx[h];
    const int* mp = mask + (size_t)b * Ldim * Hdim + h;
    const float* tp = t + b * Ldim;
    for (int l = 0; l < Ldim; l++) {
        float tc = tp[l];
        float dt = (l == 0) ? 0.f : (tc - tprev);
        tprev = tc;
        float m = (float)mp[l * Hdim];
        float delta = dt + (1.f - mprev) * dprev;
        float gx = expf(-fmaxf(0.f, wg * delta + bg));
        float x  = C[(l << 9) + h];
        int gi = ((b * Ldim + l) << 9) + h;
        g_delta[gi] = delta;
        g_xhat[gi]  = m * x + (1.f - m) * (gx * xl + (1.f - gx) * xm);
        xl = m * x + (1.f - m) * xl;
        dprev = delta; mprev = m;
    }
}

// =============================================================================
// tf32 mma GEMMs (128x128x16 tiles, 8 warps)
// =============================================================================
#define ASTR 20
#define BSTR 136

__global__ void __launch_bounds__(256) k_gh_mma(const float* __restrict__ Bw,
                                                const float* __restrict__ bias) {
    __shared__ unsigned As[2][128 * ASTR];
    __shared__ unsigned Bs[2][16 * BSTR];
    const int tid = threadIdx.x;
    const int bn = blockIdx.x * 128, bm = blockIdx.y * 128;
    const int wid = tid >> 5, lane = tid & 31;
    const int wm = (wid >> 2) * 64, wn = (wid & 3) * 32;
    const int g = lane >> 2, tg = lane & 3;
    const int arow = tid >> 2, ac4 = (tid & 3) * 4;
    const int brow = tid >> 5, bc4 = lane * 4;

    float acc[4][4][4];
    #pragma unroll
    for (int i = 0; i < 4; i++)
        #pragma unroll
        for (int j = 0; j < 4; j++)
            #pragma unroll
            for (int q = 0; q < 4; q++) acc[i][j][q] = 0.f;

    float4 av0, av1, bv0, bv1;
    av0 = *(const float4*)&g_delta[(size_t)(bm + arow) * Hdim + ac4];
    av1 = *(const float4*)&g_delta[(size_t)(bm + arow + 64) * Hdim + ac4];
    bv0 = *(const float4*)&Bw[(size_t)(brow) * Hdim + bn + bc4];
    bv1 = *(const float4*)&Bw[(size_t)(brow + 8) * Hdim + bn + bc4];
    {
        unsigned* A = As[0]; unsigned* B = Bs[0];
        A[arow * ASTR + ac4 + 0] = f2tf32(av0.x); A[arow * ASTR + ac4 + 1] = f2tf32(av0.y);
        A[arow * ASTR + ac4 + 2] = f2tf32(av0.z); A[arow * ASTR + ac4 + 3] = f2tf32(av0.w);
        A[(arow + 64) * ASTR + ac4 + 0] = f2tf32(av1.x); A[(arow + 64) * ASTR + ac4 + 1] = f2tf32(av1.y);
        A[(arow + 64) * ASTR + ac4 + 2] = f2tf32(av1.z); A[(arow + 64) * ASTR + ac4 + 3] = f2tf32(av1.w);
        B[brow * BSTR + bc4 + 0] = f2tf32(bv0.x); B[brow * BSTR + bc4 + 1] = f2tf32(bv0.y);
        B[brow * BSTR + bc4 + 2] = f2tf32(bv0.z); B[brow * BSTR + bc4 + 3] = f2tf32(bv0.w);
        B[(brow + 8) * BSTR + bc4 + 0] = f2tf32(bv1.x); B[(brow + 8) * BSTR + bc4 + 1] = f2tf32(bv1.y);
        B[(brow + 8) * BSTR + bc4 + 2] = f2tf32(bv1.z); B[(brow + 8) * BSTR + bc4 + 3] = f2tf32(bv1.w);
    }
    __syncthreads();

    const int KT = Hdim / 16;
    for (int kt = 0; kt < KT; kt++) {
        if (kt + 1 < KT) {
            int k0 = (kt + 1) * 16;
            av0 = *(const float4*)&g_delta[(size_t)(bm + arow) * Hdim + k0 + ac4];
            av1 = *(const float4*)&g_delta[(size_t)(bm + arow + 64) * Hdim + k0 + ac4];
            bv0 = *(const float4*)&Bw[(size_t)(k0 + brow) * Hdim + bn + bc4];
            bv1 = *(const float4*)&Bw[(size_t)(k0 + brow + 8) * Hdim + bn + bc4];
        }
        const unsigned* A = As[kt & 1];
        const unsigned* B = Bs[kt & 1];
        #pragma unroll
        for (int ks = 0; ks < 2; ks++) {
            unsigned af[4][4], bf[4][2];
            #pragma unroll
            for (int mt = 0; mt < 4; mt++) {
                int mb = wm + mt * 16;
                af[mt][0] = A[(mb + g) * ASTR + ks * 8 + tg];
                af[mt][1] = A[(mb + g + 8) * ASTR + ks * 8 + tg];
                af[mt][2] = A[(mb + g) * ASTR + ks * 8 + tg + 4];
                af[mt][3] = A[(mb + g + 8) * ASTR + ks * 8 + tg + 4];
            }
            #pragma unroll
            for (int nt = 0; nt < 4; nt++) {
                int nb = wn + nt * 8;
                bf[nt][0] = B[(ks * 8 + tg) * BSTR + nb + g];
                bf[nt][1] = B[(ks * 8 + tg + 4) * BSTR + nb + g];
            }
            #pragma unroll
            for (int mt = 0; mt < 4; mt++)
                #pragma unroll
                for (int nt = 0; nt < 4; nt++)
                    mma_tf32(acc[mt][nt], af[mt], bf[nt]);
        }
        if (kt + 1 < KT) {
            unsigned* An = As[(kt + 1) & 1]; unsigned* Bn = Bs[(kt + 1) & 1];
            An[arow * ASTR + ac4 + 0] = f2tf32(av0.x); An[arow * ASTR + ac4 + 1] = f2tf32(av0.y);
            An[arow * ASTR + ac4 + 2] = f2tf32(av0.z); An[arow * ASTR + ac4 + 3] = f2tf32(av0.w);
            An[(arow + 64) * ASTR + ac4 + 0] = f2tf32(av1.x); An[(arow + 64) * ASTR + ac4 + 1] = f2tf32(av1.y);
            An[(arow + 64) * ASTR + ac4 + 2] = f2tf32(av1.z); An[(arow + 64) * ASTR + ac4 + 3] = f2tf32(av1.w);
            Bn[brow * BSTR + bc4 + 0] = f2tf32(bv0.x); Bn[brow * BSTR + bc4 + 1] = f2tf32(bv0.y);
            Bn[brow * BSTR + bc4 + 2] = f2tf32(bv0.z); Bn[brow * BSTR + bc4 + 3] = f2tf32(bv0.w);
            Bn[(brow + 8) * BSTR + bc4 + 0] = f2tf32(bv1.x); Bn[(brow + 8) * BSTR + bc4 + 1] = f2tf32(bv1.y);
            Bn[(brow + 8) * BSTR + bc4 + 2] = f2tf32(bv1.z); Bn[(brow + 8) * BSTR + bc4 + 3] = f2tf32(bv1.w);
        }
        __syncthreads();
    }

    #pragma unroll
    for (int mt = 0; mt < 4; mt++) {
        #pragma unroll
        for (int nt = 0; nt < 4; nt++) {
            int col = bn + wn + nt * 8 + tg * 2;
            float b0 = bias[col], b1 = bias[col + 1];
            int r0 = bm + wm + mt * 16 + g;
            float2 o0, o1;
            o0.x = expf(-fmaxf(0.f, acc[mt][nt][0] + b0));
            o0.y = expf(-fmaxf(0.f, acc[mt][nt][1] + b1));
            o1.x = expf(-fmaxf(0.f, acc[mt][nt][2] + b0));
            o1.y = expf(-fmaxf(0.f, acc[mt][nt][3] + b1));
            *(float2*)&g_gammah[(size_t)r0 * Hdim + col] = o0;
            *(float2*)&g_gammah[(size_t)(r0 + 8) * Hdim + col] = o1;
        }
    }
}

__global__ void __launch_bounds__(256) k_pre_mma(const int* __restrict__ mask,
                                                 const float* __restrict__ Wx,
                                                 const float* __restrict__ Wm,
                                                 const float* __restrict__ bias) {
    __shared__ unsigned As[2][128 * ASTR];
    __shared__ unsigned Bs[2][16 * BSTR];
    const int tid = threadIdx.x;
    const int bn = blockIdx.x * 128, bm = blockIdx.y * 128;
    const int wid = tid >> 5, lane = tid & 31;
    const int wm = (wid >> 2) * 64, wn = (wid & 3) * 32;
    const int g = lane >> 2, tg = lane & 3;
    const int arow = tid >> 2, ac4 = (tid & 3) * 4;
    const int brow = tid >> 5, bc4 = lane * 4;

    float acc[4][4][4];
    #pragma unroll
    for (int i = 0; i < 4; i++)
        #pragma unroll
        for (int j = 0; j < 4; j++)
            #pragma unroll
            for (int q = 0; q < 4; q++) acc[i][j][q] = 0.f;

    float4 av0, av1, bv0, bv1;
    av0 = *(const float4*)&g_xhat[(size_t)(bm + arow) * Hdim + ac4];
    av1 = *(const float4*)&g_xhat[(size_t)(bm + arow + 64) * Hdim + ac4];
    bv0 = *(const float4*)&Wx[(size_t)(brow) * H3 + bn + bc4];
    bv1 = *(const float4*)&Wx[(size_t)(brow + 8) * H3 + bn + bc4];
    {
        unsigned* A = As[0]; unsigned* B = Bs[0];
        A[arow * ASTR + ac4 + 0] = f2tf32(av0.x); A[arow * ASTR + ac4 + 1] = f2tf32(av0.y);
        A[arow * ASTR + ac4 + 2] = f2tf32(av0.z); A[arow * ASTR + ac4 + 3] = f2tf32(av0.w);
        A[(arow + 64) * ASTR + ac4 + 0] = f2tf32(av1.x); A[(arow + 64) * ASTR + ac4 + 1] = f2tf32(av1.y);
        A[(arow + 64) * ASTR + ac4 + 2] = f2tf32(av1.z); A[(arow + 64) * ASTR + ac4 + 3] = f2tf32(av1.w);
        B[brow * BSTR + bc4 + 0] = f2tf32(bv0.x); B[brow * BSTR + bc4 + 1] = f2tf32(bv0.y);
        B[brow * BSTR + bc4 + 2] = f2tf32(bv0.z); B[brow * BSTR + bc4 + 3] = f2tf32(bv0.w);
        B[(brow + 8) * BSTR + bc4 + 0] = f2tf32(bv1.x); B[(brow + 8) * BSTR + bc4 + 1] = f2tf32(bv1.y);
        B[(brow + 8) * BSTR + bc4 + 2] = f2tf32(bv1.z); B[(brow + 8) * BSTR + bc4 + 3] = f2tf32(bv1.w);
    }
    __syncthreads();

    const int KT = 64;
    for (int kt = 0; kt < KT; kt++) {
        if (kt + 1 < KT) {
            int nkt = kt + 1;
            int k0 = (nkt & 31) * 16;
            if (nkt < 32) {
                av0 = *(const float4*)&g_xhat[(size_t)(bm + arow) * Hdim + k0 + ac4];
                av1 = *(const float4*)&g_xhat[(size_t)(bm + arow + 64) * Hdim + k0 + ac4];
                bv0 = *(const float4*)&Wx[(size_t)(k0 + brow) * H3 + bn + bc4];
                bv1 = *(const float4*)&Wx[(size_t)(k0 + brow + 8) * H3 + bn + bc4];
            } else {
                int4 m0 = *(const int4*)&mask[(size_t)(bm + arow) * Hdim + k0 + ac4];
                int4 m1 = *(const int4*)&mask[(size_t)(bm + arow + 64) * Hdim + k0 + ac4];
                av0 = make_float4((float)m0.x, (float)m0.y, (float)m0.z, (float)m0.w);
                av1 = make_float4((float)m1.x, (float)m1.y, (float)m1.z, (float)m1.w);
                bv0 = *(const float4*)&Wm[(size_t)(k0 + brow) * H3 + bn + bc4];
                bv1 = *(const float4*)&Wm[(size_t)(k0 + brow + 8) * H3 + bn + bc4];
            }
        }
        const unsigned* A = As[kt & 1];
        const unsigned* B = Bs[kt & 1];
        #pragma unroll
        for (int ks = 0; ks < 2; ks++) {
            unsigned af[4][4], bf[4][2];
            #pragma unroll
            for (int mt = 0; mt < 4; mt++) {
                int mb = wm + mt * 16;
                af[mt][0] = A[(mb + g) * ASTR + ks * 8 + tg];
                af[mt][1] = A[(mb + g + 8) * ASTR + ks * 8 + tg];
                af[mt][2] = A[(mb + g) * ASTR + ks * 8 + tg + 4];
                af[mt][3] = A[(mb + g + 8) * ASTR + ks * 8 + tg + 4];
            }
            #pragma unroll
            for (int nt = 0; nt < 4; nt++) {
                int nb = wn + nt * 8;
                bf[nt][0] = B[(ks * 8 + tg) * BSTR + nb + g];
                bf[nt][1] = B[(ks * 8 + tg + 4) * BSTR + nb + g];
            }
            #pragma unroll
            for (int mt = 0; mt < 4; mt++)
                #pragma unroll
                for (int nt = 0; nt < 4; nt++)
                    mma_tf32(acc[mt][nt], af[mt], bf[nt]);
        }
        if (kt + 1 < KT) {
            unsigned* An = As[(kt + 1) & 1]; unsigned* Bn = Bs[(kt + 1) & 1];
            An[arow * ASTR + ac4 + 0] = f2tf32(av0.x); An[arow * ASTR + ac4 + 1] = f2tf32(av0.y);
            An[arow * ASTR + ac4 + 2] = f2tf32(av0.z); An[arow * ASTR + ac4 + 3] = f2tf32(av0.w);
            An[(arow + 64) * ASTR + ac4 + 0] = f2tf32(av1.x); An[(arow + 64) * ASTR + ac4 + 1] = f2tf32(av1.y);
            An[(arow + 64) * ASTR + ac4 + 2] = f2tf32(av1.z); An[(arow + 64) * ASTR + ac4 + 3] = f2tf32(av1.w);
            Bn[brow * BSTR + bc4 + 0] = f2tf32(bv0.x); Bn[brow * BSTR + bc4 + 1] = f2tf32(bv0.y);
            Bn[brow * BSTR + bc4 + 2] = f2tf32(bv0.z); Bn[brow * BSTR + bc4 + 3] = f2tf32(bv0.w);
            Bn[(brow + 8) * BSTR + bc4 + 0] = f2tf32(bv1.x); Bn[(brow + 8) * BSTR + bc4 + 1] = f2tf32(bv1.y);
            Bn[(brow + 8) * BSTR + bc4 + 2] = f2tf32(bv1.z); Bn[(brow + 8) * BSTR + bc4 + 3] = f2tf32(bv1.w);
        }
        __syncthreads();
    }

    #pragma unroll
    for (int mt = 0; mt < 4; mt++) {
        #pragma unroll
        for (int nt = 0; nt < 4; nt++) {
            int col = bn + wn + nt * 8 + tg * 2;
            float b0 = bias[col], b1 = bias[col + 1];
            int r0 = bm + wm + mt * 16 + g;
            float2 o0, o1;
            o0.x = acc[mt][nt][0] + b0; o0.y = acc[mt][nt][1] + b1;
            o1.x = acc[mt][nt][2] + b0; o1.y = acc[mt][nt][3] + b1;
            *(float2*)&g_pre[(size_t)r0 * H3 + col] = o0;
            *(float2*)&g_pre[(size_t)(r0 + 8) * H3 + col] = o1;
        }
    }
}

// ---------------- K6 (mma): out = h_seq @ W_out + b_out ----------------------
__global__ void __launch_bounds__(256) k_out_mma(const float* __restrict__ Bw,
                                                 const float* __restrict__ bias,
                                                 float* __restrict__ out) {
    __shared__ unsigned As[2][128 * ASTR];
    __shared__ unsigned Bs[2][16 * BSTR];
    const int tid = threadIdx.x;
    const int bn = blockIdx.x * 128, bm = blockIdx.y * 128;
    const int wid = tid >> 5, lane = tid & 31;
    const int wm = (wid >> 2) * 64, wn = (wid & 3) * 32;
    const int g = lane >> 2, tg = lane & 3;
    const int arow = tid >> 2, ac4 = (tid & 3) * 4;
    const int brow = tid >> 5, bc4 = lane * 4;

    float acc[4][4][4];
    #pragma unroll
    for (int i = 0; i < 4; i++)
        #pragma unroll
        for (int j = 0; j < 4; j++)
            #pragma unroll
            for (int q = 0; q < 4; q++) acc[i][j][q] = 0.f;

    float4 av0, av1, bv0, bv1;
    av0 = *(const float4*)&g_hseq[(size_t)(bm + arow) * Hdim + ac4];
    av1 = *(const float4*)&g_hseq[(size_t)(bm + arow + 64) * Hdim + ac4];
    bv0 = *(const float4*)&Bw[(size_t)(brow) * OUTD + bn + bc4];
    bv1 = *(const float4*)&Bw[(size_t)(brow + 8) * OUTD + bn + bc4];
    {
        unsigned* A = As[0]; unsigned* B = Bs[0];
        A[arow * ASTR + ac4 + 0] = f2tf32(av0.x); A[arow * ASTR + ac4 + 1] = f2tf32(av0.y);
        A[arow * ASTR + ac4 + 2] = f2tf32(av0.z); A[arow * ASTR + ac4 + 3] = f2tf32(av0.w);
        A[(arow + 64) * ASTR + ac4 + 0] = f2tf32(av1.x); A[(arow + 64) * ASTR + ac4 + 1] = f2tf32(av1.y);
        A[(arow + 64) * ASTR + ac4 + 2] = f2tf32(av1.z); A[(arow + 64) * ASTR + ac4 + 3] = f2tf32(av1.w);
        B[brow * BSTR + bc4 + 0] = f2tf32(bv0.x); B[brow * BSTR + bc4 + 1] = f2tf32(bv0.y);
        B[brow * BSTR + bc4 + 2] = f2tf32(bv0.z); B[brow * BSTR + bc4 + 3] = f2tf32(bv0.w);
        B[(brow + 8) * BSTR + bc4 + 0] = f2tf32(bv1.x); B[(brow + 8) * BSTR + bc4 + 1] = f2tf32(bv1.y);
        B[(brow + 8) * BSTR + bc4 + 2] = f2tf32(bv1.z); B[(brow + 8) * BSTR + bc4 + 3] = f2tf32(bv1.w);
    }
    __syncthreads();

    const int KT = Hdim / 16;
    for (int kt = 0; kt < KT; kt++) {
        if (kt + 1 < KT) {
            int k0 = (kt + 1) * 16;
            av0 = *(const float4*)&g_hseq[(size_t)(bm + arow) * Hdim + k0 + ac4];
            av1 = *(const float4*)&g_hseq[(size_t)(bm + arow + 64) * Hdim + k0 + ac4];
            bv0 = *(const float4*)&Bw[(size_t)(k0 + brow) * OUTD + bn + bc4];
            bv1 = *(const float4*)&Bw[(size_t)(k0 + brow + 8) * OUTD + bn + bc4];
        }
        const unsigned* A = As[kt & 1];
        const unsigned* B = Bs[kt & 1];
        #pragma unroll
        for (int ks = 0; ks < 2; ks++) {
            unsigned af[4][4], bf[4][2];
            #pragma unroll
            for (int mt = 0; mt < 4; mt++) {
                int mb = wm + mt * 16;
                af[mt][0] = A[(mb + g) * ASTR + ks * 8 + tg];
                af[mt][1] = A[(mb + g + 8) * ASTR + ks * 8 + tg];
                af[mt][2] = A[(mb + g) * ASTR + ks * 8 + tg + 4];
                af[mt][3] = A[(mb + g + 8) * ASTR + ks * 8 + tg + 4];
            }
            #pragma unroll
            for (int nt = 0; nt < 4; nt++) {
                int nb = wn + nt * 8;
                bf[nt][0] = B[(ks * 8 + tg) * BSTR + nb + g];
                bf[nt][1] = B[(ks * 8 + tg + 4) * BSTR + nb + g];
            }
            #pragma unroll
            for (int mt = 0; mt < 4; mt++)
                #pragma unroll
                for (int nt = 0; nt < 4; nt++)
                    mma_tf32(acc[mt][nt], af[mt], bf[nt]);
        }
        if (kt + 1 < KT) {
            unsigned* An = As[(kt + 1) & 1]; unsigned* Bn = Bs[(kt + 1) & 1];
            An[arow * ASTR + ac4 + 0] = f2tf32(av0.x); An[arow * ASTR + ac4 + 1] = f2tf32(av0.y);
            An[arow * ASTR + ac4 + 2] = f2tf32(av0.z); An[arow * ASTR + ac4 + 3] = f2tf32(av0.w);
            An[(arow + 64) * ASTR + ac4 + 0] = f2tf32(av1.x); An[(arow + 64) * ASTR + ac4 + 1] = f2tf32(av1.y);
            An[(arow + 64) * ASTR + ac4 + 2] = f2tf32(av1.z); An[(arow + 64) * ASTR + ac4 + 3] = f2tf32(av1.w);
            Bn[brow * BSTR + bc4 + 0] = f2tf32(bv0.x); Bn[brow * BSTR + bc4 + 1] = f2tf32(bv0.y);
            Bn[brow * BSTR + bc4 + 2] = f2tf32(bv0.z); Bn[brow * BSTR + bc4 + 3] = f2tf32(bv0.w);
            Bn[(brow + 8) * BSTR + bc4 + 0] = f2tf32(bv1.x); Bn[(brow + 8) * BSTR + bc4 + 1] = f2tf32(bv1.y);
            Bn[(brow + 8) * BSTR + bc4 + 2] = f2tf32(bv1.z); Bn[(brow + 8) * BSTR + bc4 + 3] = f2tf32(bv1.w);
        }
        __syncthreads();
    }

    #pragma unroll
    for (int mt = 0; mt < 4; mt++) {
        #pragma unroll
        for (int nt = 0; nt < 4; nt++) {
            int col = bn + wn + nt * 8 + tg * 2;
            float b0 = bias[col], b1 = bias[col + 1];
            int r0 = bm + wm + mt * 16 + g;
            float2 o0, o1;
            o0.x = acc[mt][nt][0] + b0; o0.y = acc[mt][nt][1] + b1;
            o1.x = acc[mt][nt][2] + b0; o1.y = acc[mt][nt][3] + b1;
            *(float2*)&out[(size_t)r0 * OUTD + col] = o0;
            *(float2*)&out[(size_t)(r0 + 8) * OUTD + col] = o1;
        }
    }
}

// =============================================================================
// K5: persistent sequential recurrence — rebuilt.
// 128 blocks = 4 independent row-groups x 32 col-blocks. f32x2 packed FMA,
// full-K smem A tile, 8-way K-split + smem reduction, per-group barriers.
// =============================================================================
#define OFF_WH1 0                 // [512][32] k-major
#define OFF_WH3 16384             // [512][16] k-major
#define OFF_A   24576             // [32][521] row-major padded
#define ASTRIDE 521
#define OFF_RED 41248             // [8][32][36]
#define RSTR1   36
#define RKG1    (32*RSTR1)        // 1152
#define RSTR2   20
#define RKG2    (32*RSTR2)        // 640
#define SMEM_SEQ ((OFF_RED + 8*RKG1) * 4)   // 201856 B

__global__ void __launch_bounds__(256, 1) k_seq(const float* __restrict__ Wh) {
    extern __shared__ float sm[];
    float* Wh1p = sm + OFF_WH1;
    float* Wh3p = sm + OFF_WH3;
    float* Ab   = sm + OFF_A;
    float* Red  = sm + OFF_RED;

    const int tid = threadIdx.x;
    const int blk = blockIdx.x;
    const int rg  = blk >> 5;            // 0..3 (independent batch groups)
    const int tn  = blk & 31;
    const int m0  = rg * 32;
    const int n0  = tn * 32;             // GEMM1 cols
    const int n02 = tn * 16;             // GEMM2 cols

    // cache Wh panels (k-major)
    for (int i = tid; i < 512 * 8; i += 256) {
        int k = i >> 3, c4 = (i & 7) * 4;
        *(float4*)&Wh1p[k * 32 + c4] = *(const float4*)&Wh[(size_t)k * H3 + n0 + c4];
    }
    for (int i = tid; i < 512 * 4; i += 256) {
        int k = i >> 2, c4 = (i & 3) * 4;
        *(float4*)&Wh3p[k * 16 + c4] = *(const float4*)&Wh[(size_t)k * H3 + 1024 + n02 + c4];
    }
    if (tn == 0)
        for (int i = tid; i < 32 * 512; i += 256) g_h[m0 * 512 + i] = 0.f;
    groupbar(rg);

    // producer mapping: row pr, k = pc + 32j + comp
    const int pr = tid >> 3;             // 0..31
    const int pc = (tid & 7) * 4;        // 0..28
    // compute mapping: warp = k-group
    const int kg    = tid >> 5;          // 0..7
    const int t32   = tid & 31;
    const int r0c   = (t32 >> 2) * 4;    // 0,4,...,28
    const int c0g1  = (t32 & 3) * 8;     // 0,8,16,24
    const int c0g2  = (t32 & 3) * 4;     // 0,4,8,12
    const int kbase = kg * 64;

    for (int step = 0; step < Ldim; step++) {
        // ---------- produce A = gamma(step) ⊙ h ----------
        {
            const float* hrow = g_h + (m0 + pr) * 512;
            const float* grow = g_gammah + (size_t)((m0 + pr) * Ldim + step) * 512;
            #pragma unroll
            for (int j = 0; j < 16; j++) {
                int k = pc + 32 * j;
                float4 h4 = __ldcg((const float4*)(hrow + k));
                float4 g4 = *(const float4*)(grow + k);
                float* d = &Ab[pr * ASTRIDE + k];
                d[0] = h4.x * g4.x; d[1] = h4.y * g4.y;
                d[2] = h4.z * g4.z; d[3] = h4.w * g4.w;
            }
        }
        __syncthreads();
        // ---------- GEMM1: 4r x 8c per thread over 64 k ----------
        {
            ull acc[4][4];
            #pragma unroll
            for (int i = 0; i < 4; i++)
                #pragma unroll
                for (int j = 0; j < 4; j++) acc[i][j] = 0ull;
            #pragma unroll 8
            for (int kk = 0; kk < 64; kk++) {
                int k = kbase + kk;
                ulonglong2 bA = *(const ulonglong2*)&Wh1p[k * 32 + c0g1];
                ulonglong2 bB = *(const ulonglong2*)&Wh1p[k * 32 + c0g1 + 4];
                float a0 = Ab[(r0c + 0) * ASTRIDE + k];
                float a1 = Ab[(r0c + 1) * ASTRIDE + k];
                float a2 = Ab[(r0c + 2) * ASTRIDE + k];
                float a3 = Ab[(r0c + 3) * ASTRIDE + k];
                ull p0 = pack2(a0), p1 = pack2(a1), p2 = pack2(a2), p3 = pack2(a3);
                ffma2(acc[0][0], p0, bA.x); ffma2(acc[0][1], p0, bA.y);
                ffma2(acc[0][2], p0, bB.x); ffma2(acc[0][3], p0, bB.y);
                ffma2(acc[1][0], p1, bA.x); ffma2(acc[1][1], p1, bA.y);
                ffma2(acc[1][2], p1, bB.x); ffma2(acc[1][3], p1, bB.y);
                ffma2(acc[2][0], p2, bA.x); ffma2(acc[2][1], p2, bA.y);
                ffma2(acc[2][2], p2, bB.x); ffma2(acc[2][3], p2, bB.y);
                ffma2(acc[3][0], p3, bA.x); ffma2(acc[3][1], p3, bA.y);
                ffma2(acc[3][2], p3, bB.x); ffma2(acc[3][3], p3, bB.y);
            }
            // partials -> Red[kg][r][36]
            #pragma unroll
            for (int i = 0; i < 4; i++)
                #pragma unroll
                for (int j = 0; j < 4; j++)
                    *(ull*)&Red[kg * RKG1 + (r0c + i) * RSTR1 + c0g1 + 2 * j] = acc[i][j];
        }
        __syncthreads();
        // ---------- reduce + epilogue (4 outputs/thread) ----------
        {
            int idx = tid * 4;
            int r = idx >> 5, c = idx & 31;
            float4 s = *(float4*)&Red[r * RSTR1 + c];
            #pragma unroll
            for (int q = 1; q < 8; q++) {
                float4 v = *(float4*)&Red[q * RKG1 + r * RSTR1 + c];
                s.x += v.x; s.y += v.y; s.z += v.z; s.w += v.w;
            }
            int b = m0 + r;
            float4 pre4 = __ldcg((const float4*)&g_pre[(size_t)(b * Ldim + step) * H3 + n0 + c]);
            float s0 = sigmoidf_(s.x + pre4.x);
            float s1 = sigmoidf_(s.y + pre4.y);
            float s2 = sigmoidf_(s.z + pre4.z);
            float s3 = sigmoidf_(s.w + pre4.w);
            if (n0 < 512) {
                *(float4*)&g_z[b * 512 + n0 + c] = make_float4(s0, s1, s2, s3);
            } else {
                int nn = n0 - 512 + c;
                float4 gm = *(const float4*)&g_gammah[(size_t)(b * Ldim + step) * 512 + nn];
                float4 h4 = __ldcg((const float4*)&g_h[b * 512 + nn]);
                *(float4*)&g_rh[b * 512 + nn] = make_float4(
                    s0 * gm.x * h4.x, s1 * gm.y * h4.y, s2 * gm.z * h4.z, s3 * gm.w * h4.w);
            }
        }
        groupbar(rg);

        // ---------- produce A = rh ----------
        {
            const float* rrow = g_rh + (m0 + pr) * 512;
            #pragma unroll
            for (int j = 0; j < 16; j++) {
                int k = pc + 32 * j;
                float4 r4 = __ldcg((const float4*)(rrow + k));
                float* d = &Ab[pr * ASTRIDE + k];
                d[0] = r4.x; d[1] = r4.y; d[2] = r4.z; d[3] = r4.w;
            }
        }
        __syncthreads();
        // ---------- GEMM2: 4r x 4c per thread over 64 k ----------
        {
            ull acc[4][2];
            #pragma unroll
            for (int i = 0; i < 4; i++) { acc[i][0] = 0ull; acc[i][1] = 0ull; }
            #pragma unroll 8
            for (int kk = 0; kk < 64; kk++) {
                int k = kbase + kk;
                ulonglong2 bA = *(const ulonglong2*)&Wh3p[k * 16 + c0g2];
                float a0 = Ab[(r0c + 0) * ASTRIDE + k];
                float a1 = Ab[(r0c + 1) * ASTRIDE + k];
                float a2 = Ab[(r0c + 2) * ASTRIDE + k];
                float a3 = Ab[(r0c + 3) * ASTRIDE + k];
                ull p0 = pack2(a0), p1 = pack2(a1), p2 = pack2(a2), p3 = pack2(a3);
                ffma2(acc[0][0], p0, bA.x); ffma2(acc[0][1], p0, bA.y);
                ffma2(acc[1][0], p1, bA.x); ffma2(acc[1][1], p1, bA.y);
                ffma2(acc[2][0], p2, bA.x); ffma2(acc[2][1], p2, bA.y);
                ffma2(acc[3][0], p3, bA.x); ffma2(acc[3][1], p3, bA.y);
            }
            #pragma unroll
            for (int i = 0; i < 4; i++) {
                *(ull*)&Red[kg * RKG2 + (r0c + i) * RSTR2 + c0g2]     = acc[i][0];
                *(ull*)&Red[kg * RKG2 + (r0c + i) * RSTR2 + c0g2 + 2] = acc[i][1];
            }
        }
        __syncthreads();
        // ---------- reduce + epilogue (2 outputs/thread): gates + h update ----
        {
            int idx = tid * 2;
            int r = idx >> 4, cc = idx & 15;
            float2 s = *(float2*)&Red[r * RSTR2 + cc];
            #pragma unroll
            for (int q = 1; q < 8; q++) {
                float2 v = *(float2*)&Red[q * RKG2 + r * RSTR2 + cc];
                s.x += v.x; s.y += v.y;
            }
            int b = m0 + r, n = n02 + cc;
            float2 pre2 = __ldcg((const float2*)&g_pre[(size_t)(b * Ldim + step) * H3 + 1024 + n]);
            float2 gm = *(const float2*)&g_gammah[(size_t)(b * Ldim + step) * 512 + n];
            float2 h2 = *(const float2*)&g_h[b * 512 + n];
            float2 z2 = *(const float2*)&g_z[b * 512 + n];
            float ht0 = tanhf(s.x + pre2.x), ht1 = tanhf(s.y + pre2.y);
            float hd0 = gm.x * h2.x, hd1 = gm.y * h2.y;
            float hn0 = (1.f - z2.x) * hd0 + z2.x * ht0;
            float hn1 = (1.f - z2.y) * hd1 + z2.y * ht1;
            *(float2*)&g_h[b * 512 + n] = make_float2(hn0, hn1);
            *(float2*)&g_hseq[(size_t)(b * Ldim + step) * 512 + n] = make_float2(hn0, hn1);
        }
        groupbar(rg);
    }
}

// ---------------- launch -----------------------------------------------------
extern "C" void kernel_launch(void* const* d_in, const int* in_sizes, int n_in,
                              void* d_out, int out_size) {
    const float* C     = (const float*)d_in[0];
    const float* t     = (const float*)d_in[1];
    const int*   mask  = (const int*)  d_in[2];
    const float* Wx    = (const float*)d_in[3];
    const float* Wh    = (const float*)d_in[4];
    const float* Wm    = (const float*)d_in[5];
    const float* bvec  = (const float*)d_in[6];
    const float* w_gx  = (const float*)d_in[7];
    const float* b_gx  = (const float*)d_in[8];
    const float* W_gh  = (const float*)d_in[9];
    const float* b_gh  = (const float*)d_in[10];
    const float* W_out = (const float*)d_in[11];
    const float* b_out = (const float*)d_in[12];
    float* out = (float*)d_out;

    cudaFuncSetAttribute(k_seq, cudaFuncAttributeMaxDynamicSharedMemorySize, SMEM_SEQ);

    k_xmean<<<Bdim * Hdim / 256, 256>>>(C, mask);
    k_scan <<<Bdim * Hdim / 256, 256>>>(C, t, mask, w_gx, b_gx);
    k_gh_mma <<<dim3(Hdim / 128, BL / 128), 256>>>(W_gh, b_gh);
    k_pre_mma<<<dim3(H3 / 128,  BL / 128), 256>>>(mask, Wx, Wm, bvec);
    k_seq<<<NBLK, 256, SMEM_SEQ>>>(Wh);
    k_out_mma<<<dim3(OUTD / 128, BL / 128), 256>>>(W_out, b_out, out);
}

// round 5
// speedup vs baseline: 2.8569x; 1.2206x over previous
#include <cuda_runtime.h>
#include <math.h>

#define Bdim 128
#define Ldim 256
#define Hdim 512
#define H3   1536
#define OUTD 256
#define BL   (Bdim*Ldim)   // 32768
#define NBLK 128

// ---------------- scratch (device globals) ----------------------------------
__device__ float g_xmean[Bdim*Hdim];
__device__ float g_delta[BL*Hdim];
__device__ float g_xhat [BL*Hdim];
__device__ float g_gammah[BL*Hdim];
__device__ float g_pre  [BL*H3];
__device__ float g_hseq [BL*Hdim];
__device__ float g_h    [Bdim*Hdim];
__device__ float g_z    [Bdim*Hdim];
__device__ float g_rh   [Bdim*Hdim];
__device__ unsigned g_arr4[4*32];
__device__ volatile unsigned g_rel4[4*32];

// ---------------- per-row-group barrier (32 blocks) -------------------------
__device__ __forceinline__ void groupbar(int rg) {
    __syncthreads();
    if (threadIdx.x == 0) {
        __threadfence();
        unsigned gen = g_rel4[rg * 32];
        if (atomicInc((unsigned*)&g_arr4[rg * 32], 31u) == 31u) {
            __threadfence();
            g_rel4[rg * 32] = gen + 1u;
        } else {
            while (g_rel4[rg * 32] == gen) { __nanosleep(32); }
        }
    }
    __syncthreads();
}

__device__ __forceinline__ float sigmoidf_(float x) { return 1.f / (1.f + expf(-x)); }

__device__ __forceinline__ unsigned f2tf32(float f) {
    unsigned r; asm("cvt.rna.tf32.f32 %0, %1;" : "=r"(r) : "f"(f)); return r;
}
__device__ __forceinline__ void mma_tf32(float* c, const unsigned* a, const unsigned* b) {
    asm volatile("mma.sync.aligned.m16n8k8.row.col.f32.tf32.tf32.f32 "
        "{%0,%1,%2,%3}, {%4,%5,%6,%7}, {%8,%9}, {%0,%1,%2,%3};"
        : "+f"(c[0]), "+f"(c[1]), "+f"(c[2]), "+f"(c[3])
        : "r"(a[0]), "r"(a[1]), "r"(a[2]), "r"(a[3]), "r"(b[0]), "r"(b[1]));
}

// ---------------- K1: x_mean -------------------------------------------------
__global__ void __launch_bounds__(256) k_xmean(const float* __restrict__ C,
                                               const int* __restrict__ mask) {
    int idx = blockIdx.x * 256 + threadIdx.x;
    int b = idx >> 9, h = idx & 511;
    const int* mp = mask + (size_t)b * Ldim * Hdim + h;
    float s = 0.f, cnt = 0.f;
    #pragma unroll 4
    for (int l = 0; l < Ldim; l++) {
        float m = (float)mp[l * Hdim];
        s   += m * C[l * Hdim + h];
        cnt += m;
    }
    g_xmean[idx] = s / fmaxf(cnt, 1.f);
}

// ---------------- K2: elementwise scans --------------------------------------
__global__ void __launch_bounds__(256) k_scan(const float* __restrict__ C,
                                              const float* __restrict__ t,
                                              const int* __restrict__ mask,
                                              const float* __restrict__ w_gx,
                                              const float* __restrict__ b_gx) {
    int idx = blockIdx.x * 256 + threadIdx.x;
    int b = idx >> 9, h = idx & 511;
    float xm = g_xmean[idx];
    float xl = xm, dprev = 0.f, mprev = 1.f, tprev = 0.f;
    float wg = w_gx[h], bg = b_gx[h];
    const int* mp = mask + (size_t)b * Ldim * Hdim + h;
    const float* tp = t + b * Ldim;
    for (int l = 0; l < Ldim; l++) {
        float tc = tp[l];
        float dt = (l == 0) ? 0.f : (tc - tprev);
        tprev = tc;
        float m = (float)mp[l * Hdim];
        float delta = dt + (1.f - mprev) * dprev;
        float gx = expf(-fmaxf(0.f, wg * delta + bg));
        float x  = C[(l << 9) + h];
        int gi = ((b * Ldim + l) << 9) + h;
        g_delta[gi] = delta;
        g_xhat[gi]  = m * x + (1.f - m) * (gx * xl + (1.f - gx) * xm);
        xl = m * x + (1.f - m) * xl;
        dprev = delta; mprev = m;
    }
}

// =============================================================================
// tf32 mma GEMMs (128x128x16 tiles, 8 warps), 2 blocks/SM
// =============================================================================
#define ASTR 20
#define BSTR 136

__global__ void __launch_bounds__(256, 2) k_gh_mma(const float* __restrict__ Bw,
                                                   const float* __restrict__ bias) {
    __shared__ unsigned As[2][128 * ASTR];
    __shared__ unsigned Bs[2][16 * BSTR];
    const int tid = threadIdx.x;
    const int bn = blockIdx.x * 128, bm = blockIdx.y * 128;
    const int wid = tid >> 5, lane = tid & 31;
    const int wm = (wid >> 2) * 64, wn = (wid & 3) * 32;
    const int g = lane >> 2, tg = lane & 3;
    const int arow = tid >> 2, ac4 = (tid & 3) * 4;
    const int brow = tid >> 5, bc4 = lane * 4;

    float acc[4][4][4];
    #pragma unroll
    for (int i = 0; i < 4; i++)
        #pragma unroll
        for (int j = 0; j < 4; j++)
            #pragma unroll
            for (int q = 0; q < 4; q++) acc[i][j][q] = 0.f;

    float4 av0, av1, bv0, bv1;
    av0 = *(const float4*)&g_delta[(size_t)(bm + arow) * Hdim + ac4];
    av1 = *(const float4*)&g_delta[(size_t)(bm + arow + 64) * Hdim + ac4];
    bv0 = *(const float4*)&Bw[(size_t)(brow) * Hdim + bn + bc4];
    bv1 = *(const float4*)&Bw[(size_t)(brow + 8) * Hdim + bn + bc4];
    {
        unsigned* A = As[0]; unsigned* B = Bs[0];
        A[arow * ASTR + ac4 + 0] = f2tf32(av0.x); A[arow * ASTR + ac4 + 1] = f2tf32(av0.y);
        A[arow * ASTR + ac4 + 2] = f2tf32(av0.z); A[arow * ASTR + ac4 + 3] = f2tf32(av0.w);
        A[(arow + 64) * ASTR + ac4 + 0] = f2tf32(av1.x); A[(arow + 64) * ASTR + ac4 + 1] = f2tf32(av1.y);
        A[(arow + 64) * ASTR + ac4 + 2] = f2tf32(av1.z); A[(arow + 64) * ASTR + ac4 + 3] = f2tf32(av1.w);
        B[brow * BSTR + bc4 + 0] = f2tf32(bv0.x); B[brow * BSTR + bc4 + 1] = f2tf32(bv0.y);
        B[brow * BSTR + bc4 + 2] = f2tf32(bv0.z); B[brow * BSTR + bc4 + 3] = f2tf32(bv0.w);
        B[(brow + 8) * BSTR + bc4 + 0] = f2tf32(bv1.x); B[(brow + 8) * BSTR + bc4 + 1] = f2tf32(bv1.y);
        B[(brow + 8) * BSTR + bc4 + 2] = f2tf32(bv1.z); B[(brow + 8) * BSTR + bc4 + 3] = f2tf32(bv1.w);
    }
    __syncthreads();

    const int KT = Hdim / 16;
    for (int kt = 0; kt < KT; kt++) {
        if (kt + 1 < KT) {
            int k0 = (kt + 1) * 16;
            av0 = *(const float4*)&g_delta[(size_t)(bm + arow) * Hdim + k0 + ac4];
            av1 = *(const float4*)&g_delta[(size_t)(bm + arow + 64) * Hdim + k0 + ac4];
            bv0 = *(const float4*)&Bw[(size_t)(k0 + brow) * Hdim + bn + bc4];
            bv1 = *(const float4*)&Bw[(size_t)(k0 + brow + 8) * Hdim + bn + bc4];
        }
        const unsigned* A = As[kt & 1];
        const unsigned* B = Bs[kt & 1];
        #pragma unroll
        for (int ks = 0; ks < 2; ks++) {
            unsigned af[4][4], bf[4][2];
            #pragma unroll
            for (int mt = 0; mt < 4; mt++) {
                int mb = wm + mt * 16;
                af[mt][0] = A[(mb + g) * ASTR + ks * 8 + tg];
                af[mt][1] = A[(mb + g + 8) * ASTR + ks * 8 + tg];
                af[mt][2] = A[(mb + g) * ASTR + ks * 8 + tg + 4];
                af[mt][3] = A[(mb + g + 8) * ASTR + ks * 8 + tg + 4];
            }
            #pragma unroll
            for (int nt = 0; nt < 4; nt++) {
                int nb = wn + nt * 8;
                bf[nt][0] = B[(ks * 8 + tg) * BSTR + nb + g];
                bf[nt][1] = B[(ks * 8 + tg + 4) * BSTR + nb + g];
            }
            #pragma unroll
            for (int mt = 0; mt < 4; mt++)
                #pragma unroll
                for (int nt = 0; nt < 4; nt++)
                    mma_tf32(acc[mt][nt], af[mt], bf[nt]);
        }
        if (kt + 1 < KT) {
            unsigned* An = As[(kt + 1) & 1]; unsigned* Bn = Bs[(kt + 1) & 1];
            An[arow * ASTR + ac4 + 0] = f2tf32(av0.x); An[arow * ASTR + ac4 + 1] = f2tf32(av0.y);
            An[arow * ASTR + ac4 + 2] = f2tf32(av0.z); An[arow * ASTR + ac4 + 3] = f2tf32(av0.w);
            An[(arow + 64) * ASTR + ac4 + 0] = f2tf32(av1.x); An[(arow + 64) * ASTR + ac4 + 1] = f2tf32(av1.y);
            An[(arow + 64) * ASTR + ac4 + 2] = f2tf32(av1.z); An[(arow + 64) * ASTR + ac4 + 3] = f2tf32(av1.w);
            Bn[brow * BSTR + bc4 + 0] = f2tf32(bv0.x); Bn[brow * BSTR + bc4 + 1] = f2tf32(bv0.y);
            Bn[brow * BSTR + bc4 + 2] = f2tf32(bv0.z); Bn[brow * BSTR + bc4 + 3] = f2tf32(bv0.w);
            Bn[(brow + 8) * BSTR + bc4 + 0] = f2tf32(bv1.x); Bn[(brow + 8) * BSTR + bc4 + 1] = f2tf32(bv1.y);
            Bn[(brow + 8) * BSTR + bc4 + 2] = f2tf32(bv1.z); Bn[(brow + 8) * BSTR + bc4 + 3] = f2tf32(bv1.w);
        }
        __syncthreads();
    }

    #pragma unroll
    for (int mt = 0; mt < 4; mt++) {
        #pragma unroll
        for (int nt = 0; nt < 4; nt++) {
            int col = bn + wn + nt * 8 + tg * 2;
            float b0 = bias[col], b1 = bias[col + 1];
            int r0 = bm + wm + mt * 16 + g;
            float2 o0, o1;
            o0.x = expf(-fmaxf(0.f, acc[mt][nt][0] + b0));
            o0.y = expf(-fmaxf(0.f, acc[mt][nt][1] + b1));
            o1.x = expf(-fmaxf(0.f, acc[mt][nt][2] + b0));
            o1.y = expf(-fmaxf(0.f, acc[mt][nt][3] + b1));
            *(float2*)&g_gammah[(size_t)r0 * Hdim + col] = o0;
            *(float2*)&g_gammah[(size_t)(r0 + 8) * Hdim + col] = o1;
        }
    }
}

__global__ void __launch_bounds__(256, 2) k_pre_mma(const int* __restrict__ mask,
                                                    const float* __restrict__ Wx,
                                                    const float* __restrict__ Wm,
                                                    const float* __restrict__ bias) {
    __shared__ unsigned As[2][128 * ASTR];
    __shared__ unsigned Bs[2][16 * BSTR];
    const int tid = threadIdx.x;
    const int bn = blockIdx.x * 128, bm = blockIdx.y * 128;
    const int wid = tid >> 5, lane = tid & 31;
    const int wm = (wid >> 2) * 64, wn = (wid & 3) * 32;
    const int g = lane >> 2, tg = lane & 3;
    const int arow = tid >> 2, ac4 = (tid & 3) * 4;
    const int brow = tid >> 5, bc4 = lane * 4;

    float acc[4][4][4];
    #pragma unroll
    for (int i = 0; i < 4; i++)
        #pragma unroll
        for (int j = 0; j < 4; j++)
            #pragma unroll
            for (int q = 0; q < 4; q++) acc[i][j][q] = 0.f;

    float4 av0, av1, bv0, bv1;
    av0 = *(const float4*)&g_xhat[(size_t)(bm + arow) * Hdim + ac4];
    av1 = *(const float4*)&g_xhat[(size_t)(bm + arow + 64) * Hdim + ac4];
    bv0 = *(const float4*)&Wx[(size_t)(brow) * H3 + bn + bc4];
    bv1 = *(const float4*)&Wx[(size_t)(brow + 8) * H3 + bn + bc4];
    {
        unsigned* A = As[0]; unsigned* B = Bs[0];
        A[arow * ASTR + ac4 + 0] = f2tf32(av0.x); A[arow * ASTR + ac4 + 1] = f2tf32(av0.y);
        A[arow * ASTR + ac4 + 2] = f2tf32(av0.z); A[arow * ASTR + ac4 + 3] = f2tf32(av0.w);
        A[(arow + 64) * ASTR + ac4 + 0] = f2tf32(av1.x); A[(arow + 64) * ASTR + ac4 + 1] = f2tf32(av1.y);
        A[(arow + 64) * ASTR + ac4 + 2] = f2tf32(av1.z); A[(arow + 64) * ASTR + ac4 + 3] = f2tf32(av1.w);
        B[brow * BSTR + bc4 + 0] = f2tf32(bv0.x); B[brow * BSTR + bc4 + 1] = f2tf32(bv0.y);
        B[brow * BSTR + bc4 + 2] = f2tf32(bv0.z); B[brow * BSTR + bc4 + 3] = f2tf32(bv0.w);
        B[(brow + 8) * BSTR + bc4 + 0] = f2tf32(bv1.x); B[(brow + 8) * BSTR + bc4 + 1] = f2tf32(bv1.y);
        B[(brow + 8) * BSTR + bc4 + 2] = f2tf32(bv1.z); B[(brow + 8) * BSTR + bc4 + 3] = f2tf32(bv1.w);
    }
    __syncthreads();

    const int KT = 64;
    for (int kt = 0; kt < KT; kt++) {
        if (kt + 1 < KT) {
            int nkt = kt + 1;
            int k0 = (nkt & 31) * 16;
            if (nkt < 32) {
                av0 = *(const float4*)&g_xhat[(size_t)(bm + arow) * Hdim + k0 + ac4];
                av1 = *(const float4*)&g_xhat[(size_t)(bm + arow + 64) * Hdim + k0 + ac4];
                bv0 = *(const float4*)&Wx[(size_t)(k0 + brow) * H3 + bn + bc4];
                bv1 = *(const float4*)&Wx[(size_t)(k0 + brow + 8) * H3 + bn + bc4];
            } else {
                int4 m0 = *(const int4*)&mask[(size_t)(bm + arow) * Hdim + k0 + ac4];
                int4 m1 = *(const int4*)&mask[(size_t)(bm + arow + 64) * Hdim + k0 + ac4];
                av0 = make_float4((float)m0.x, (float)m0.y, (float)m0.z, (float)m0.w);
                av1 = make_float4((float)m1.x, (float)m1.y, (float)m1.z, (float)m1.w);
                bv0 = *(const float4*)&Wm[(size_t)(k0 + brow) * H3 + bn + bc4];
                bv1 = *(const float4*)&Wm[(size_t)(k0 + brow + 8) * H3 + bn + bc4];
            }
        }
        const unsigned* A = As[kt & 1];
        const unsigned* B = Bs[kt & 1];
        #pragma unroll
        for (int ks = 0; ks < 2; ks++) {
            unsigned af[4][4], bf[4][2];
            #pragma unroll
            for (int mt = 0; mt < 4; mt++) {
                int mb = wm + mt * 16;
                af[mt][0] = A[(mb + g) * ASTR + ks * 8 + tg];
                af[mt][1] = A[(mb + g + 8) * ASTR + ks * 8 + tg];
                af[mt][2] = A[(mb + g) * ASTR + ks * 8 + tg + 4];
                af[mt][3] = A[(mb + g + 8) * ASTR + ks * 8 + tg + 4];
            }
            #pragma unroll
            for (int nt = 0; nt < 4; nt++) {
                int nb = wn + nt * 8;
                bf[nt][0] = B[(ks * 8 + tg) * BSTR + nb + g];
                bf[nt][1] = B[(ks * 8 + tg + 4) * BSTR + nb + g];
            }
            #pragma unroll
            for (int mt = 0; mt < 4; mt++)
                #pragma unroll
                for (int nt = 0; nt < 4; nt++)
                    mma_tf32(acc[mt][nt], af[mt], bf[nt]);
        }
        if (kt + 1 < KT) {
            unsigned* An = As[(kt + 1) & 1]; unsigned* Bn = Bs[(kt + 1) & 1];
            An[arow * ASTR + ac4 + 0] = f2tf32(av0.x); An[arow * ASTR + ac4 + 1] = f2tf32(av0.y);
            An[arow * ASTR + ac4 + 2] = f2tf32(av0.z); An[arow * ASTR + ac4 + 3] = f2tf32(av0.w);
            An[(arow + 64) * ASTR + ac4 + 0] = f2tf32(av1.x); An[(arow + 64) * ASTR + ac4 + 1] = f2tf32(av1.y);
            An[(arow + 64) * ASTR + ac4 + 2] = f2tf32(av1.z); An[(arow + 64) * ASTR + ac4 + 3] = f2tf32(av1.w);
            Bn[brow * BSTR + bc4 + 0] = f2tf32(bv0.x); Bn[brow * BSTR + bc4 + 1] = f2tf32(bv0.y);
            Bn[brow * BSTR + bc4 + 2] = f2tf32(bv0.z); Bn[brow * BSTR + bc4 + 3] = f2tf32(bv0.w);
            Bn[(brow + 8) * BSTR + bc4 + 0] = f2tf32(bv1.x); Bn[(brow + 8) * BSTR + bc4 + 1] = f2tf32(bv1.y);
            Bn[(brow + 8) * BSTR + bc4 + 2] = f2tf32(bv1.z); Bn[(brow + 8) * BSTR + bc4 + 3] = f2tf32(bv1.w);
        }
        __syncthreads();
    }

    #pragma unroll
    for (int mt = 0; mt < 4; mt++) {
        #pragma unroll
        for (int nt = 0; nt < 4; nt++) {
            int col = bn + wn + nt * 8 + tg * 2;
            float b0 = bias[col], b1 = bias[col + 1];
            int r0 = bm + wm + mt * 16 + g;
            float2 o0, o1;
            o0.x = acc[mt][nt][0] + b0; o0.y = acc[mt][nt][1] + b1;
            o1.x = acc[mt][nt][2] + b0; o1.y = acc[mt][nt][3] + b1;
            *(float2*)&g_pre[(size_t)r0 * H3 + col] = o0;
            *(float2*)&g_pre[(size_t)(r0 + 8) * H3 + col] = o1;
        }
    }
}

// ---------------- K6 (mma): out = h_seq @ W_out + b_out ----------------------
__global__ void __launch_bounds__(256, 2) k_out_mma(const float* __restrict__ Bw,
                                                    const float* __restrict__ bias,
                                                    float* __restrict__ out) {
    __shared__ unsigned As[2][128 * ASTR];
    __shared__ unsigned Bs[2][16 * BSTR];
    const int tid = threadIdx.x;
    const int bn = blockIdx.x * 128, bm = blockIdx.y * 128;
    const int wid = tid >> 5, lane = tid & 31;
    const int wm = (wid >> 2) * 64, wn = (wid & 3) * 32;
    const int g = lane >> 2, tg = lane & 3;
    const int arow = tid >> 2, ac4 = (tid & 3) * 4;
    const int brow = tid >> 5, bc4 = lane * 4;

    float acc[4][4][4];
    #pragma unroll
    for (int i = 0; i < 4; i++)
        #pragma unroll
        for (int j = 0; j < 4; j++)
            #pragma unroll
            for (int q = 0; q < 4; q++) acc[i][j][q] = 0.f;

    float4 av0, av1, bv0, bv1;
    av0 = *(const float4*)&g_hseq[(size_t)(bm + arow) * Hdim + ac4];
    av1 = *(const float4*)&g_hseq[(size_t)(bm + arow + 64) * Hdim + ac4];
    bv0 = *(const float4*)&Bw[(size_t)(brow) * OUTD + bn + bc4];
    bv1 = *(const float4*)&Bw[(size_t)(brow + 8) * OUTD + bn + bc4];
    {
        unsigned* A = As[0]; unsigned* B = Bs[0];
        A[arow * ASTR + ac4 + 0] = f2tf32(av0.x); A[arow * ASTR + ac4 + 1] = f2tf32(av0.y);
        A[arow * ASTR + ac4 + 2] = f2tf32(av0.z); A[arow * ASTR + ac4 + 3] = f2tf32(av0.w);
        A[(arow + 64) * ASTR + ac4 + 0] = f2tf32(av1.x); A[(arow + 64) * ASTR + ac4 + 1] = f2tf32(av1.y);
        A[(arow + 64) * ASTR + ac4 + 2] = f2tf32(av1.z); A[(arow + 64) * ASTR + ac4 + 3] = f2tf32(av1.w);
        B[brow * BSTR + bc4 + 0] = f2tf32(bv0.x); B[brow * BSTR + bc4 + 1] = f2tf32(bv0.y);
        B[brow * BSTR + bc4 + 2] = f2tf32(bv0.z); B[brow * BSTR + bc4 + 3] = f2tf32(bv0.w);
        B[(brow + 8) * BSTR + bc4 + 0] = f2tf32(bv1.x); B[(brow + 8) * BSTR + bc4 + 1] = f2tf32(bv1.y);
        B[(brow + 8) * BSTR + bc4 + 2] = f2tf32(bv1.z); B[(brow + 8) * BSTR + bc4 + 3] = f2tf32(bv1.w);
    }
    __syncthreads();

    const int KT = Hdim / 16;
    for (int kt = 0; kt < KT; kt++) {
        if (kt + 1 < KT) {
            int k0 = (kt + 1) * 16;
            av0 = *(const float4*)&g_hseq[(size_t)(bm + arow) * Hdim + k0 + ac4];
            av1 = *(const float4*)&g_hseq[(size_t)(bm + arow + 64) * Hdim + k0 + ac4];
            bv0 = *(const float4*)&Bw[(size_t)(k0 + brow) * OUTD + bn + bc4];
            bv1 = *(const float4*)&Bw[(size_t)(k0 + brow + 8) * OUTD + bn + bc4];
        }
        const unsigned* A = As[kt & 1];
        const unsigned* B = Bs[kt & 1];
        #pragma unroll
        for (int ks = 0; ks < 2; ks++) {
            unsigned af[4][4], bf[4][2];
            #pragma unroll
            for (int mt = 0; mt < 4; mt++) {
                int mb = wm + mt * 16;
                af[mt][0] = A[(mb + g) * ASTR + ks * 8 + tg];
                af[mt][1] = A[(mb + g + 8) * ASTR + ks * 8 + tg];
                af[mt][2] = A[(mb + g) * ASTR + ks * 8 + tg + 4];
                af[mt][3] = A[(mb + g + 8) * ASTR + ks * 8 + tg + 4];
            }
            #pragma unroll
            for (int nt = 0; nt < 4; nt++) {
                int nb = wn + nt * 8;
                bf[nt][0] = B[(ks * 8 + tg) * BSTR + nb + g];
                bf[nt][1] = B[(ks * 8 + tg + 4) * BSTR + nb + g];
            }
            #pragma unroll
            for (int mt = 0; mt < 4; mt++)
                #pragma unroll
                for (int nt = 0; nt < 4; nt++)
                    mma_tf32(acc[mt][nt], af[mt], bf[nt]);
        }
        if (kt + 1 < KT) {
            unsigned* An = As[(kt + 1) & 1]; unsigned* Bn = Bs[(kt + 1) & 1];
            An[arow * ASTR + ac4 + 0] = f2tf32(av0.x); An[arow * ASTR + ac4 + 1] = f2tf32(av0.y);
            An[arow * ASTR + ac4 + 2] = f2tf32(av0.z); An[arow * ASTR + ac4 + 3] = f2tf32(av0.w);
            An[(arow + 64) * ASTR + ac4 + 0] = f2tf32(av1.x); An[(arow + 64) * ASTR + ac4 + 1] = f2tf32(av1.y);
            An[(arow + 64) * ASTR + ac4 + 2] = f2tf32(av1.z); An[(arow + 64) * ASTR + ac4 + 3] = f2tf32(av1.w);
            Bn[brow * BSTR + bc4 + 0] = f2tf32(bv0.x); Bn[brow * BSTR + bc4 + 1] = f2tf32(bv0.y);
            Bn[brow * BSTR + bc4 + 2] = f2tf32(bv0.z); Bn[brow * BSTR + bc4 + 3] = f2tf32(bv0.w);
            Bn[(brow + 8) * BSTR + bc4 + 0] = f2tf32(bv1.x); Bn[(brow + 8) * BSTR + bc4 + 1] = f2tf32(bv1.y);
            Bn[(brow + 8) * BSTR + bc4 + 2] = f2tf32(bv1.z); Bn[(brow + 8) * BSTR + bc4 + 3] = f2tf32(bv1.w);
        }
        __syncthreads();
    }

    #pragma unroll
    for (int mt = 0; mt < 4; mt++) {
        #pragma unroll
        for (int nt = 0; nt < 4; nt++) {
            int col = bn + wn + nt * 8 + tg * 2;
            float b0 = bias[col], b1 = bias[col + 1];
            int r0 = bm + wm + mt * 16 + g;
            float2 o0, o1;
            o0.x = acc[mt][nt][0] + b0; o0.y = acc[mt][nt][1] + b1;
            o1.x = acc[mt][nt][2] + b0; o1.y = acc[mt][nt][3] + b1;
            *(float2*)&out[(size_t)r0 * OUTD + col] = o0;
            *(float2*)&out[(size_t)(r0 + 8) * OUTD + col] = o1;
        }
    }
}

// =============================================================================
// K5: persistent sequential recurrence — tensor-core (tf32 mma) version.
// 128 blocks = 4 row-groups x 32 col-blocks. Per warp: K-slice 64, full output
// tile via m16n8k8 fragments; 8-way partials reduced in smem.
// =============================================================================
#define OFF_WH1 0                    // tf32 [512][40] k-major (conflict-free)
#define WS1     40
#define OFF_WH3 20480                // tf32 [512][20] k-major
#define WS3     20
#define OFF_AB  30720                // tf32 [32][516]
#define AS      516
#define OFF_RED 47232                // float [8][32][36] / [8][32][20]
#define RSTR1   36
#define RKG1    (32*RSTR1)
#define RSTR2   20
#define RKG2    (32*RSTR2)
#define SMEM_SEQ ((OFF_RED + 8*RKG1) * 4)   // 225792 B

__global__ void __launch_bounds__(256, 1) k_seq(const float* __restrict__ Wh) {
    extern __shared__ unsigned smu[];
    unsigned* Wh1t = smu + OFF_WH1;
    unsigned* Wh3t = smu + OFF_WH3;
    unsigned* Ab   = smu + OFF_AB;
    float*    Red  = (float*)(smu + OFF_RED);

    const int tid = threadIdx.x;
    const int blk = blockIdx.x;
    const int rg  = blk >> 5;
    const int tn  = blk & 31;
    const int m0  = rg * 32;
    const int n0  = tn * 32;
    const int n02 = tn * 16;

    // convert Wh panels to tf32 once
    for (int i = tid; i < 512 * 32; i += 256) {
        int k = i >> 5, n = i & 31;
        Wh1t[k * WS1 + n] = f2tf32(Wh[(size_t)k * H3 + n0 + n]);
    }
    for (int i = tid; i < 512 * 16; i += 256) {
        int k = i >> 4, n = i & 15;
        Wh3t[k * WS3 + n] = f2tf32(Wh[(size_t)k * H3 + 1024 + n02 + n]);
    }
    if (tn == 0)
        for (int i = tid; i < 32 * 512; i += 256) g_h[m0 * 512 + i] = 0.f;
    groupbar(rg);

    const int lane = tid & 31, kg = tid >> 5;
    const int g = lane >> 2, tg = lane & 3;
    const int kbase = kg * 64;
    const int pr = tid >> 3, pc = (tid & 7) * 4;

    for (int step = 0; step < Ldim; step++) {
        // ---------- produce A = gamma(step) ⊙ h (tf32) ----------
        {
            const float* hrow = g_h + (m0 + pr) * 512;
            const float* grow = g_gammah + (size_t)((m0 + pr) * Ldim + step) * 512;
            #pragma unroll
            for (int j = 0; j < 16; j++) {
                int k = pc + 32 * j;
                float4 h4 = __ldcg((const float4*)(hrow + k));
                float4 g4 = *(const float4*)(grow + k);
                uint4 o;
                o.x = f2tf32(h4.x * g4.x); o.y = f2tf32(h4.y * g4.y);
                o.z = f2tf32(h4.z * g4.z); o.w = f2tf32(h4.w * g4.w);
                *(uint4*)&Ab[pr * AS + k] = o;
            }
        }
        __syncthreads();
        // ---------- GEMM1 (mma): 32x32, K-slice 64 per warp ----------
        {
            float acc[2][4][4];
            #pragma unroll
            for (int mt = 0; mt < 2; mt++)
                #pragma unroll
                for (int nt = 0; nt < 4; nt++)
                    #pragma unroll
                    for (int q = 0; q < 4; q++) acc[mt][nt][q] = 0.f;
            #pragma unroll
            for (int ks = 0; ks < 8; ks++) {
                int k = kbase + ks * 8;
                unsigned af[2][4];
                #pragma unroll
                for (int mt = 0; mt < 2; mt++) {
                    int mb = mt * 16;
                    af[mt][0] = Ab[(mb + g) * AS + k + tg];
                    af[mt][1] = Ab[(mb + g + 8) * AS + k + tg];
                    af[mt][2] = Ab[(mb + g) * AS + k + tg + 4];
                    af[mt][3] = Ab[(mb + g + 8) * AS + k + tg + 4];
                }
                unsigned bf[4][2];
                #pragma unroll
                for (int nt = 0; nt < 4; nt++) {
                    bf[nt][0] = Wh1t[(k + tg) * WS1 + nt * 8 + g];
                    bf[nt][1] = Wh1t[(k + tg + 4) * WS1 + nt * 8 + g];
                }
                #pragma unroll
                for (int mt = 0; mt < 2; mt++)
                    #pragma unroll
                    for (int nt = 0; nt < 4; nt++)
                        mma_tf32(acc[mt][nt], af[mt], bf[nt]);
            }
            #pragma unroll
            for (int mt = 0; mt < 2; mt++)
                #pragma unroll
                for (int nt = 0; nt < 4; nt++) {
                    float* base = &Red[kg * RKG1 + (mt * 16 + g) * RSTR1 + nt * 8 + tg * 2];
                    *(float2*)base = make_float2(acc[mt][nt][0], acc[mt][nt][1]);
                    *(float2*)(base + 8 * RSTR1) = make_float2(acc[mt][nt][2], acc[mt][nt][3]);
                }
        }
        __syncthreads();
        // ---------- reduce + epilogue (4 outputs/thread) ----------
        {
            int idx = tid * 4;
            int r = idx >> 5, c = idx & 31;
            float4 s = *(float4*)&Red[r * RSTR1 + c];
            #pragma unroll
            for (int q = 1; q < 8; q++) {
                float4 v = *(float4*)&Red[q * RKG1 + r * RSTR1 + c];
                s.x += v.x; s.y += v.y; s.z += v.z; s.w += v.w;
            }
            int b = m0 + r;
            float4 pre4 = __ldcg((const float4*)&g_pre[(size_t)(b * Ldim + step) * H3 + n0 + c]);
            float s0 = sigmoidf_(s.x + pre4.x);
            float s1 = sigmoidf_(s.y + pre4.y);
            float s2 = sigmoidf_(s.z + pre4.z);
            float s3 = sigmoidf_(s.w + pre4.w);
            if (n0 < 512) {
                *(float4*)&g_z[b * 512 + n0 + c] = make_float4(s0, s1, s2, s3);
            } else {
                int nn = n0 - 512 + c;
                float4 gm = *(const float4*)&g_gammah[(size_t)(b * Ldim + step) * 512 + nn];
                float4 h4 = __ldcg((const float4*)&g_h[b * 512 + nn]);
                *(float4*)&g_rh[b * 512 + nn] = make_float4(
                    s0 * gm.x * h4.x, s1 * gm.y * h4.y, s2 * gm.z * h4.z, s3 * gm.w * h4.w);
            }
        }
        groupbar(rg);

        // ---------- produce A = rh (tf32) ----------
        {
            const float* rrow = g_rh + (m0 + pr) * 512;
            #pragma unroll
            for (int j = 0; j < 16; j++) {
                int k = pc + 32 * j;
                float4 r4 = __ldcg((const float4*)(rrow + k));
                uint4 o;
                o.x = f2tf32(r4.x); o.y = f2tf32(r4.y);
                o.z = f2tf32(r4.z); o.w = f2tf32(r4.w);
                *(uint4*)&Ab[pr * AS + k] = o;
            }
        }
        __syncthreads();
        // ---------- GEMM2 (mma): 32x16, K-slice 64 per warp ----------
        {
            float acc[2][2][4];
            #pragma unroll
            for (int mt = 0; mt < 2; mt++)
                #pragma unroll
                for (int nt = 0; nt < 2; nt++)
                    #pragma unroll
                    for (int q = 0; q < 4; q++) acc[mt][nt][q] = 0.f;
            #pragma unroll
            for (int ks = 0; ks < 8; ks++) {
                int k = kbase + ks * 8;
                unsigned af[2][4];
                #pragma unroll
                for (int mt = 0; mt < 2; mt++) {
                    int mb = mt * 16;
                    af[mt][0] = Ab[(mb + g) * AS + k + tg];
                    af[mt][1] = Ab[(mb + g + 8) * AS + k + tg];
                    af[mt][2] = Ab[(mb + g) * AS + k + tg + 4];
                    af[mt][3] = Ab[(mb + g + 8) * AS + k + tg + 4];
                }
                unsigned bf[2][2];
                #pragma unroll
                for (int nt = 0; nt < 2; nt++) {
                    bf[nt][0] = Wh3t[(k + tg) * WS3 + nt * 8 + g];
                    bf[nt][1] = Wh3t[(k + tg + 4) * WS3 + nt * 8 + g];
                }
                #pragma unroll
                for (int mt = 0; mt < 2; mt++)
                    #pragma unroll
                    for (int nt = 0; nt < 2; nt++)
                        mma_tf32(acc[mt][nt], af[mt], bf[nt]);
            }
            #pragma unroll
            for (int mt = 0; mt < 2; mt++)
                #pragma unroll
                for (int nt = 0; nt < 2; nt++) {
                    float* base = &Red[kg * RKG2 + (mt * 16 + g) * RSTR2 + nt * 8 + tg * 2];
                    *(float2*)base = make_float2(acc[mt][nt][0], acc[mt][nt][1]);
                    *(float2*)(base + 8 * RSTR2) = make_float2(acc[mt][nt][2], acc[mt][nt][3]);
                }
        }
        __syncthreads();
        // ---------- reduce2 + epilogue: gates + h update ----------
        {
            int idx = tid * 2;
            int r = idx >> 4, cc = idx & 15;
            float2 s = *(float2*)&Red[r * RSTR2 + cc];
            #pragma unroll
            for (int q = 1; q < 8; q++) {
                float2 v = *(float2*)&Red[q * RKG2 + r * RSTR2 + cc];
                s.x += v.x; s.y += v.y;
            }
            int b = m0 + r, n = n02 + cc;
            float2 pre2 = __ldcg((const float2*)&g_pre[(size_t)(b * Ldim + step) * H3 + 1024 + n]);
            float2 gm = *(const float2*)&g_gammah[(size_t)(b * Ldim + step) * 512 + n];
            float2 h2 = *(const float2*)&g_h[b * 512 + n];
            float2 z2 = *(const float2*)&g_z[b * 512 + n];
            float ht0 = tanhf(s.x + pre2.x), ht1 = tanhf(s.y + pre2.y);
            float hd0 = gm.x * h2.x, hd1 = gm.y * h2.y;
            float hn0 = (1.f - z2.x) * hd0 + z2.x * ht0;
            float hn1 = (1.f - z2.y) * hd1 + z2.y * ht1;
            *(float2*)&g_h[b * 512 + n] = make_float2(hn0, hn1);
            *(float2*)&g_hseq[(size_t)(b * Ldim + step) * 512 + n] = make_float2(hn0, hn1);
        }
        groupbar(rg);
    }
}

// ---------------- launch -----------------------------------------------------
extern "C" void kernel_launch(void* const* d_in, const int* in_sizes, int n_in,
                              void* d_out, int out_size) {
    const float* C     = (const float*)d_in[0];
    const float* t     = (const float*)d_in[1];
    const int*   mask  = (const int*)  d_in[2];
    const float* Wx    = (const float*)d_in[3];
    const float* Wh    = (const float*)d_in[4];
    const float* Wm    = (const float*)d_in[5];
    const float* bvec  = (const float*)d_in[6];
    const float* w_gx  = (const float*)d_in[7];
    const float* b_gx  = (const float*)d_in[8];
    const float* W_gh  = (const float*)d_in[9];
    const float* b_gh  = (const float*)d_in[10];
    const float* W_out = (const float*)d_in[11];
    const float* b_out = (const float*)d_in[12];
    float* out = (float*)d_out;

    cudaFuncSetAttribute(k_seq, cudaFuncAttributeMaxDynamicSharedMemorySize, SMEM_SEQ);

    k_xmean<<<Bdim * Hdim / 256, 256>>>(C, mask);
    k_scan <<<Bdim * Hdim / 256, 256>>>(C, t, mask, w_gx, b_gx);
    k_gh_mma <<<dim3(Hdim / 128, BL / 128), 256>>>(W_gh, b_gh);
    k_pre_mma<<<dim3(H3 / 128,  BL / 128), 256>>>(mask, Wx, Wm, bvec);
    k_seq<<<NBLK, 256, SMEM_SEQ>>>(Wh);
    k_out_mma<<<dim3(OUTD / 128, BL / 128), 256>>>(W_out, b_out, out);
}